// round 3
// baseline (speedup 1.0000x reference)
#include <cuda_runtime.h>
#include <math.h>

#define NPTS   65536
#define NSAMP  16
#define CDIM   256
#define CH2    32
#define NROWS  (NPTS*NSAMP)   // 1048576
#define EPSBN  1e-5

// ---------------- device scratch (static; no allocation allowed) ----------------
__device__ float g_xq[NPTS*CDIM];        // 64 MB
__device__ float g_xk[NPTS*CDIM];        // 64 MB
__device__ float g_xv[NPTS*CDIM];        // 64 MB
__device__ float g_pr1[NROWS*3];         // 12 MB
__device__ float g_h1[NROWS*CH2];        // 128 MB
__device__ double g_sp[6];               // BN_p: sum[3], sumsq[3]
__device__ double g_s1[512];             // BN_1: sum[256], sumsq[256]
__device__ double g_s2[64];              // BN_2: sum[32], sumsq[32]
__device__ float g_ap[3], g_dp[3];
__device__ float g_a1[CDIM], g_d1[CDIM];
__device__ float g_a2[CH2], g_d2[CH2];

// ---------------- K0: zero the stat accumulators (graph-replay safe) ----------------
__global__ void k_zero() {
    int t = threadIdx.x;
    if (t < 6) g_sp[t] = 0.0;
    for (int i = t; i < 512; i += 256) g_s1[i] = 0.0;
    if (t < 64) g_s2[t] = 0.0;
}

// ---------------- K1: fused QKV SGEMM  C[65536,768] = x @ [wq;wk;wv]^T + b ----------------
// BM=128, BN=64, BK=16, 256 threads, 8x4 per-thread microtile.
__global__ __launch_bounds__(256) void k_qkv(
    const float* __restrict__ x,
    const float* __restrict__ wq, const float* __restrict__ bq,
    const float* __restrict__ wk, const float* __restrict__ bk,
    const float* __restrict__ wv, const float* __restrict__ bv)
{
    __shared__ float As[16*132];   // [k][m], padded
    __shared__ float Bs[16*68];    // [k][n], padded

    const int tid = threadIdx.x;
    const int m0  = blockIdx.y * 128;
    const int bx  = blockIdx.x;           // 0..11
    const int buf = bx >> 2;              // 0=q, 1=k, 2=v
    const float* W    = (buf == 0) ? wq : (buf == 1) ? wk : wv;
    const float* Bias = (buf == 0) ? bq : (buf == 1) ? bk : bv;
    float* Cout       = (buf == 0) ? g_xq : (buf == 1) ? g_xk : g_xv;
    const int wrow0 = (bx & 3) * 64;      // column offset within this weight (0..192)

    const int aRow = tid >> 2;            // 0..63
    const int aC4  = (tid & 3) * 4;       // 0,4,8,12
    const int ty   = tid >> 4;            // 0..15
    const int tx   = tid & 15;            // 0..15

    float acc[8][4];
#pragma unroll
    for (int i = 0; i < 8; i++)
#pragma unroll
        for (int ii = 0; ii < 4; ii++) acc[i][ii] = 0.f;

    for (int k0 = 0; k0 < 256; k0 += 16) {
        float4 a0 = *(const float4*)&x[(size_t)(m0 + aRow) * 256 + k0 + aC4];
        float4 a1 = *(const float4*)&x[(size_t)(m0 + aRow + 64) * 256 + k0 + aC4];
        float4 b4 = *(const float4*)&W[(size_t)(wrow0 + aRow) * 256 + k0 + aC4];
        __syncthreads();
        As[(aC4 + 0) * 132 + aRow] = a0.x;
        As[(aC4 + 1) * 132 + aRow] = a0.y;
        As[(aC4 + 2) * 132 + aRow] = a0.z;
        As[(aC4 + 3) * 132 + aRow] = a0.w;
        As[(aC4 + 0) * 132 + aRow + 64] = a1.x;
        As[(aC4 + 1) * 132 + aRow + 64] = a1.y;
        As[(aC4 + 2) * 132 + aRow + 64] = a1.z;
        As[(aC4 + 3) * 132 + aRow + 64] = a1.w;
        Bs[(aC4 + 0) * 68 + aRow] = b4.x;
        Bs[(aC4 + 1) * 68 + aRow] = b4.y;
        Bs[(aC4 + 2) * 68 + aRow] = b4.z;
        Bs[(aC4 + 3) * 68 + aRow] = b4.w;
        __syncthreads();
#pragma unroll
        for (int k = 0; k < 16; k++) {
            float4 av0 = *(float4*)&As[k * 132 + ty * 8];
            float4 av1 = *(float4*)&As[k * 132 + ty * 8 + 4];
            float4 bv4 = *(float4*)&Bs[k * 68 + tx * 4];
            float am[8] = {av0.x, av0.y, av0.z, av0.w, av1.x, av1.y, av1.z, av1.w};
            float bn[4] = {bv4.x, bv4.y, bv4.z, bv4.w};
#pragma unroll
            for (int i = 0; i < 8; i++)
#pragma unroll
                for (int ii = 0; ii < 4; ii++)
                    acc[i][ii] = fmaf(am[i], bn[ii], acc[i][ii]);
        }
    }

    const int colIn = wrow0 + tx * 4;     // 0..255 within this weight's output
    float4 bias = *(const float4*)&Bias[colIn];
#pragma unroll
    for (int i = 0; i < 8; i++) {
        float4 o;
        o.x = acc[i][0] + bias.x;
        o.y = acc[i][1] + bias.y;
        o.z = acc[i][2] + bias.z;
        o.w = acc[i][3] + bias.w;
        *(float4*)&Cout[(size_t)(m0 + ty * 8 + i) * 256 + colIn] = o;
    }
}

// ---------------- K2: p_r1 = (p[idx]-p) @ wp1^T + bp1, store + BN_p stats ----------------
__global__ __launch_bounds__(256) void k_pr1(
    const float* __restrict__ p, const int* __restrict__ idx,
    const float* __restrict__ wp1, const float* __restrict__ bp1)
{
    const int tid = threadIdx.x;
    const int base = blockIdx.x * 1024 + tid;
    float W[9], B[3];
#pragma unroll
    for (int i = 0; i < 9; i++) W[i] = wp1[i];
#pragma unroll
    for (int i = 0; i < 3; i++) B[i] = bp1[i];

    float v6[6] = {0, 0, 0, 0, 0, 0};   // s0,s1,s2,q0,q1,q2
#pragma unroll
    for (int it = 0; it < 4; it++) {
        int i = base + it * 256;
        int n = i >> 4;
        int j = idx[i];
        float dx = p[j * 3 + 0] - p[n * 3 + 0];
        float dy = p[j * 3 + 1] - p[n * 3 + 1];
        float dz = p[j * 3 + 2] - p[n * 3 + 2];
        float r0 = fmaf(W[0], dx, fmaf(W[1], dy, fmaf(W[2], dz, B[0])));
        float r1 = fmaf(W[3], dx, fmaf(W[4], dy, fmaf(W[5], dz, B[1])));
        float r2 = fmaf(W[6], dx, fmaf(W[7], dy, fmaf(W[8], dz, B[2])));
        g_pr1[(size_t)i * 3 + 0] = r0;
        g_pr1[(size_t)i * 3 + 1] = r1;
        g_pr1[(size_t)i * 3 + 2] = r2;
        v6[0] += r0; v6[1] += r1; v6[2] += r2;
        v6[3] = fmaf(r0, r0, v6[3]);
        v6[4] = fmaf(r1, r1, v6[4]);
        v6[5] = fmaf(r2, r2, v6[5]);
    }
#pragma unroll
    for (int i = 0; i < 6; i++)
        for (int off = 16; off; off >>= 1)
            v6[i] += __shfl_down_sync(0xffffffffu, v6[i], off);

    __shared__ float wsum[8][6];
    int warp = tid >> 5, lane = tid & 31;
    if (lane == 0)
#pragma unroll
        for (int i = 0; i < 6; i++) wsum[warp][i] = v6[i];
    __syncthreads();
    if (tid < 6) {
        float tot = 0;
#pragma unroll
        for (int w = 0; w < 8; w++) tot += wsum[w][tid];
        atomicAdd(&g_sp[tid], (double)tot);
    }
}

__global__ void k_finp(const float* __restrict__ gp, const float* __restrict__ btp) {
    int c = threadIdx.x;
    if (c < 3) {
        double cnt = (double)NROWS;
        double m = g_sp[c] / cnt;
        double v = g_sp[3 + c] / cnt - m * m;
        float a = (float)((double)gp[c] / sqrt(v + EPSBN));
        g_ap[c] = a;
        g_dp[c] = btp[c] - (float)m * a;
    }
}

// ---------------- K4: BN_1 stats on w0 = xk_g - xq + p_r2 (recomputed) ----------------
__global__ __launch_bounds__(256) void k_bn1(
    const int* __restrict__ idx,
    const float* __restrict__ wp2, const float* __restrict__ bp2)
{
    __shared__ int sidx[512];
    __shared__ float st[1536];
    const int tid = threadIdx.x;
    const int n0 = blockIdx.x * 32;

    for (int i = tid; i < 512; i += 256) sidx[i] = idx[n0 * 16 + i];
    for (int i = tid; i < 1536; i += 256) {
        float v = g_pr1[(size_t)n0 * 48 + i];
        int k = i % 3;
        st[i] = fmaxf(fmaf(g_ap[k], v, g_dp[k]), 0.f);
    }
    const int c = tid;
    const float w0c = wp2[c * 3], w1c = wp2[c * 3 + 1], w2c = wp2[c * 3 + 2];
    const float bpc = bp2[c];
    float s = 0.f, q = 0.f;
    __syncthreads();

    for (int pt = 0; pt < 32; pt++) {
        float xqc = g_xq[(size_t)(n0 + pt) * 256 + c];
        int b16 = pt * 16;
#pragma unroll 4
        for (int ns = 0; ns < 16; ns++) {
            int j = sidx[b16 + ns];
            float t0 = st[(b16 + ns) * 3], t1 = st[(b16 + ns) * 3 + 1], t2 = st[(b16 + ns) * 3 + 2];
            float pr2 = fmaf(t0, w0c, fmaf(t1, w1c, fmaf(t2, w2c, bpc)));
            float w = g_xk[(size_t)j * 256 + c] - xqc + pr2;
            s += w;
            q = fmaf(w, w, q);
        }
    }
    atomicAdd(&g_s1[c], (double)s);
    atomicAdd(&g_s1[256 + c], (double)q);
}

__global__ void k_fin1(const float* __restrict__ g1, const float* __restrict__ b1) {
    int c = threadIdx.x;
    if (c < 256) {
        double cnt = (double)NROWS;
        double m = g_s1[c] / cnt;
        double v = g_s1[256 + c] / cnt - m * m;
        float a = (float)((double)g1[c] / sqrt(v + EPSBN));
        g_a1[c] = a;
        g_d1[c] = b1[c] - (float)m * a;
    }
}

// ---------------- K5: h1 = relu(bn1(w0)) @ ww1^T + bw1 (stored) + BN_2 stats ----------------
// 8 points per block (128 rows); u staged in dynamic smem; fused skinny GEMM 256->32.
#define H1_SMEM ((128*260 + 32*260 + 384) * 4 + 128 * 4)
__global__ __launch_bounds__(256) void k_h1(
    const int* __restrict__ idx,
    const float* __restrict__ wp2, const float* __restrict__ bp2,
    const float* __restrict__ ww1, const float* __restrict__ bw1)
{
    extern __shared__ float sm[];
    float* u_t  = sm;                 // [128][260]
    float* ww1s = sm + 128 * 260;     // [32][260]
    float* st   = ww1s + 32 * 260;    // [384]
    int*   sidx = (int*)(st + 384);   // [128]
    __shared__ float ssum[32], ssq[32];

    const int tid = threadIdx.x;
    const int n0 = blockIdx.x * 8;
    const int r0g = blockIdx.x * 128;

    if (tid < 128) sidx[tid] = idx[r0g + tid];
    for (int i = tid; i < 384; i += 256) {
        float v = g_pr1[(size_t)n0 * 48 + i];
        int k = i % 3;
        st[i] = fmaxf(fmaf(g_ap[k], v, g_dp[k]), 0.f);
    }
#pragma unroll
    for (int i = 0; i < 32; i++) ww1s[i * 260 + tid] = ww1[i * 256 + tid];
    if (tid < 32) { ssum[tid] = 0.f; ssq[tid] = 0.f; }

    const int c = tid;
    float xqr[8];
#pragma unroll
    for (int pt = 0; pt < 8; pt++) xqr[pt] = g_xq[(size_t)(n0 + pt) * 256 + c];
    const float w0c = wp2[c * 3], w1c = wp2[c * 3 + 1], w2c = wp2[c * 3 + 2];
    const float bpc = bp2[c];
    const float a1c = g_a1[c], d1c = g_d1[c];
    __syncthreads();

    // phase 1: u[r][c]
#pragma unroll 4
    for (int r = 0; r < 128; r++) {
        int j = sidx[r];
        float t0 = st[r * 3], t1 = st[r * 3 + 1], t2 = st[r * 3 + 2];
        float pr2 = fmaf(t0, w0c, fmaf(t1, w1c, fmaf(t2, w2c, bpc)));
        float w = g_xk[(size_t)j * 256 + c] - xqr[r >> 4] + pr2;
        u_t[r * 260 + c] = fmaxf(fmaf(a1c, w, d1c), 0.f);
    }
    __syncthreads();

    // phase 2: h1[128][32] = u[128][256] @ ww1^T
    const int rq = tid >> 3, jq = tid & 7;
    const int rr0 = rq * 4, j0 = jq * 4;
    float acc[4][4];
#pragma unroll
    for (int i = 0; i < 4; i++)
#pragma unroll
        for (int ii = 0; ii < 4; ii++) acc[i][ii] = 0.f;

    for (int k0 = 0; k0 < 256; k0 += 4) {
        float4 U[4], Wv[4];
#pragma unroll
        for (int i = 0; i < 4; i++)  U[i]  = *(float4*)&u_t[(rr0 + i) * 260 + k0];
#pragma unroll
        for (int ii = 0; ii < 4; ii++) Wv[ii] = *(float4*)&ww1s[(j0 + ii) * 260 + k0];
#pragma unroll
        for (int i = 0; i < 4; i++)
#pragma unroll
            for (int ii = 0; ii < 4; ii++) {
                acc[i][ii] = fmaf(U[i].x, Wv[ii].x, acc[i][ii]);
                acc[i][ii] = fmaf(U[i].y, Wv[ii].y, acc[i][ii]);
                acc[i][ii] = fmaf(U[i].z, Wv[ii].z, acc[i][ii]);
                acc[i][ii] = fmaf(U[i].w, Wv[ii].w, acc[i][ii]);
            }
    }

    float4 bw = *(const float4*)&bw1[j0];
    float csum[4] = {0, 0, 0, 0}, csq[4] = {0, 0, 0, 0};
#pragma unroll
    for (int i = 0; i < 4; i++) {
        float4 o;
        o.x = acc[i][0] + bw.x;
        o.y = acc[i][1] + bw.y;
        o.z = acc[i][2] + bw.z;
        o.w = acc[i][3] + bw.w;
        *(float4*)&g_h1[(size_t)(r0g + rr0 + i) * 32 + j0] = o;
        csum[0] += o.x; csq[0] = fmaf(o.x, o.x, csq[0]);
        csum[1] += o.y; csq[1] = fmaf(o.y, o.y, csq[1]);
        csum[2] += o.z; csq[2] = fmaf(o.z, o.z, csq[2]);
        csum[3] += o.w; csq[3] = fmaf(o.w, o.w, csq[3]);
    }
#pragma unroll
    for (int ii = 0; ii < 4; ii++) {
        atomicAdd(&ssum[j0 + ii], csum[ii]);
        atomicAdd(&ssq[j0 + ii], csq[ii]);
    }
    __syncthreads();
    if (tid < 32) {
        atomicAdd(&g_s2[tid], (double)ssum[tid]);
        atomicAdd(&g_s2[32 + tid], (double)ssq[tid]);
    }
}

__global__ void k_fin2(const float* __restrict__ g2, const float* __restrict__ b2) {
    int c = threadIdx.x;
    if (c < 32) {
        double cnt = (double)NROWS;
        double m = g_s2[c] / cnt;
        double v = g_s2[32 + c] / cnt - m * m;
        float a = (float)((double)g2[c] / sqrt(v + EPSBN));
        g_a2[c] = a;
        g_d2[c] = b2[c] - (float)m * a;
    }
}

// ---------------- K6: bn2+relu -> @ww2 -> softmax(ns) -> weighted gather-sum ----------------
__global__ __launch_bounds__(256) void k_out(
    const int* __restrict__ idx,
    const float* __restrict__ wp2, const float* __restrict__ bp2,
    const float* __restrict__ ww2, const float* __restrict__ bw2,
    float* __restrict__ out)
{
    __shared__ int sidx[16];
    __shared__ float st[48];
    __shared__ float sv[512];
    __shared__ float sw2[32 * 33];
    __shared__ float sh[16 * 33];

    const int tid = threadIdx.x;
    const int n = blockIdx.x;

    if (tid < 16) sidx[tid] = idx[n * 16 + tid];
    if (tid < 48) {
        float v = g_pr1[(size_t)n * 48 + tid];
        int k = tid % 3;
        st[tid] = fmaxf(fmaf(g_ap[k], v, g_dp[k]), 0.f);
    }
    {
        int t = tid;
        float hv = g_h1[(size_t)n * 512 + t];
        int j = t & 31;
        sv[t] = fmaxf(fmaf(g_a2[j], hv, g_d2[j]), 0.f);
        t = tid + 256;
        hv = g_h1[(size_t)n * 512 + t];
        j = t & 31;
        sv[t] = fmaxf(fmaf(g_a2[j], hv, g_d2[j]), 0.f);
    }
    for (int f = tid; f < 1024; f += 256) sw2[(f >> 5) * 33 + (f & 31)] = ww2[f];
    __syncthreads();

    {
        int kk = tid & 31;
        float bwv = bw2[kk];
#pragma unroll
        for (int rep = 0; rep < 2; rep++) {
            int ns = (tid >> 5) + rep * 8;
            float a = bwv;
#pragma unroll
            for (int j = 0; j < 32; j++) a = fmaf(sv[ns * 32 + j], sw2[kk * 33 + j], a);
            sh[ns * 33 + kk] = a;
        }
    }
    __syncthreads();

    if (tid < 32) {
        int kk = tid;
        float m = -1e30f;
#pragma unroll
        for (int ns = 0; ns < 16; ns++) m = fmaxf(m, sh[ns * 33 + kk]);
        float s = 0.f;
#pragma unroll
        for (int ns = 0; ns < 16; ns++) {
            float e = expf(sh[ns * 33 + kk] - m);
            sh[ns * 33 + kk] = e;
            s += e;
        }
        float inv = 1.f / s;
#pragma unroll
        for (int ns = 0; ns < 16; ns++) sh[ns * 33 + kk] *= inv;
    }
    __syncthreads();

    const int c = tid;
    const float w0c = wp2[c * 3], w1c = wp2[c * 3 + 1], w2c = wp2[c * 3 + 2];
    const float bpc = bp2[c];
    const int jl = c & 31;
    float a = 0.f;
#pragma unroll 4
    for (int ns = 0; ns < 16; ns++) {
        int j = sidx[ns];
        float t0 = st[ns * 3], t1 = st[ns * 3 + 1], t2 = st[ns * 3 + 2];
        float pr2 = fmaf(t0, w0c, fmaf(t1, w1c, fmaf(t2, w2c, bpc)));
        a = fmaf(g_xv[(size_t)j * 256 + c] + pr2, sh[ns * 33 + jl], a);
    }
    out[(size_t)n * 256 + c] = a;
}

// ---------------- launch ----------------
extern "C" void kernel_launch(void* const* d_in, const int* in_sizes, int n_in,
                              void* d_out, int out_size)
{
    (void)in_sizes; (void)n_in; (void)out_size;
    const float* p   = (const float*)d_in[0];
    const float* x   = (const float*)d_in[1];
    const int*   idx = (const int*)  d_in[2];
    const float* wq  = (const float*)d_in[3];
    const float* bq  = (const float*)d_in[4];
    const float* wk  = (const float*)d_in[5];
    const float* bk  = (const float*)d_in[6];
    const float* wv  = (const float*)d_in[7];
    const float* bv  = (const float*)d_in[8];
    const float* wp1 = (const float*)d_in[9];
    const float* bp1 = (const float*)d_in[10];
    const float* gp  = (const float*)d_in[11];
    const float* btp = (const float*)d_in[12];
    const float* wp2 = (const float*)d_in[13];
    const float* bp2 = (const float*)d_in[14];
    const float* g1  = (const float*)d_in[15];
    const float* b1  = (const float*)d_in[16];
    const float* ww1 = (const float*)d_in[17];
    const float* bw1 = (const float*)d_in[18];
    const float* g2  = (const float*)d_in[19];
    const float* b2  = (const float*)d_in[20];
    const float* ww2 = (const float*)d_in[21];
    const float* bw2 = (const float*)d_in[22];
    float* out = (float*)d_out;

    cudaFuncSetAttribute(k_h1, cudaFuncAttributeMaxDynamicSharedMemorySize, H1_SMEM);

    k_zero<<<1, 256>>>();
    k_qkv<<<dim3(12, 512), 256>>>(x, wq, bq, wk, bk, wv, bv);
    k_pr1<<<1024, 256>>>(p, idx, wp1, bp1);
    k_finp<<<1, 32>>>(gp, btp);
    k_bn1<<<2048, 256>>>(idx, wp2, bp2);
    k_fin1<<<1, 256>>>(g1, b1);
    k_h1<<<8192, 256, H1_SMEM>>>(idx, wp2, bp2, ww1, bw1);
    k_fin2<<<1, 32>>>(g2, b2);
    k_out<<<65536, 256>>>(idx, wp2, bp2, ww2, bw2, out);
}

// round 4
// speedup vs baseline: 1.0037x; 1.0037x over previous
#include <cuda_runtime.h>
#include <math.h>

#define NPTS   65536
#define NSAMP  16
#define CDIM   256
#define CH2    32
#define NROWS  (NPTS*NSAMP)   // 1048576
#define INVN   (1.0/(double)NROWS)

// ---------------- device scratch (static; no allocation allowed) ----------------
__device__ float g_xq[NPTS*CDIM];        // 64 MB
__device__ float g_xk[NPTS*CDIM];        // 64 MB
__device__ float g_xv[NPTS*CDIM];        // 64 MB
__device__ float g_pr1[NROWS*3];         // 12 MB
__device__ float g_h1[NROWS*CH2];        // 128 MB
__device__ double g_sp[6];               // BN_p: sum[3], sumsq[3]
__device__ double g_s1[512];             // BN_1: sum[256], sumsq[256]
__device__ double g_s2[64];              // BN_2: sum[32], sumsq[32]

// ---------------- K0: zero stat accumulators (graph-replay safe) ----------------
__global__ void k_zero() {
    int t = threadIdx.x;
    if (t < 6) g_sp[t] = 0.0;
    for (int i = t; i < 512; i += 256) g_s1[i] = 0.0;
    if (t < 64) g_s2[t] = 0.0;
}

// ---------------- K1: fused QKV SGEMM  [65536,768] = x @ [wq;wk;wv]^T + b ------
// BM=128, BN=128, BK=16, 256 threads, 8x8 microtile.
__global__ __launch_bounds__(256, 2) void k_qkv(
    const float* __restrict__ x,
    const float* __restrict__ wq, const float* __restrict__ bq,
    const float* __restrict__ wk, const float* __restrict__ bk,
    const float* __restrict__ wv, const float* __restrict__ bv)
{
    __shared__ float As[16 * 132];   // [k][m]
    __shared__ float Bs[16 * 132];   // [k][n]

    const int tid = threadIdx.x;
    const int m0  = blockIdx.y * 128;
    const int bx  = blockIdx.x;           // 0..5
    const int buf = bx >> 1;              // 0=q, 1=k, 2=v
    const float* W    = (buf == 0) ? wq : (buf == 1) ? wk : wv;
    const float* Bias = (buf == 0) ? bq : (buf == 1) ? bk : bv;
    float* Cout       = (buf == 0) ? g_xq : (buf == 1) ? g_xk : g_xv;
    const int wrow0 = (bx & 1) * 128;

    const int lr = tid >> 2;              // 0..63
    const int lc = (tid & 3) * 4;         // 0,4,8,12
    const int ty = tid >> 4;              // 0..15
    const int tx = tid & 15;              // 0..15

    float acc[8][8];
#pragma unroll
    for (int i = 0; i < 8; i++)
#pragma unroll
        for (int j = 0; j < 8; j++) acc[i][j] = 0.f;

    for (int k0 = 0; k0 < 256; k0 += 16) {
        float4 a0 = *(const float4*)&x[(size_t)(m0 + lr) * 256 + k0 + lc];
        float4 a1 = *(const float4*)&x[(size_t)(m0 + lr + 64) * 256 + k0 + lc];
        float4 b0 = *(const float4*)&W[(size_t)(wrow0 + lr) * 256 + k0 + lc];
        float4 b1 = *(const float4*)&W[(size_t)(wrow0 + lr + 64) * 256 + k0 + lc];
        __syncthreads();
        As[(lc + 0) * 132 + lr] = a0.x;
        As[(lc + 1) * 132 + lr] = a0.y;
        As[(lc + 2) * 132 + lr] = a0.z;
        As[(lc + 3) * 132 + lr] = a0.w;
        As[(lc + 0) * 132 + lr + 64] = a1.x;
        As[(lc + 1) * 132 + lr + 64] = a1.y;
        As[(lc + 2) * 132 + lr + 64] = a1.z;
        As[(lc + 3) * 132 + lr + 64] = a1.w;
        Bs[(lc + 0) * 132 + lr] = b0.x;
        Bs[(lc + 1) * 132 + lr] = b0.y;
        Bs[(lc + 2) * 132 + lr] = b0.z;
        Bs[(lc + 3) * 132 + lr] = b0.w;
        Bs[(lc + 0) * 132 + lr + 64] = b1.x;
        Bs[(lc + 1) * 132 + lr + 64] = b1.y;
        Bs[(lc + 2) * 132 + lr + 64] = b1.z;
        Bs[(lc + 3) * 132 + lr + 64] = b1.w;
        __syncthreads();
#pragma unroll
        for (int k = 0; k < 16; k++) {
            float4 av0 = *(float4*)&As[k * 132 + ty * 8];
            float4 av1 = *(float4*)&As[k * 132 + ty * 8 + 4];
            float4 bv0 = *(float4*)&Bs[k * 132 + tx * 8];
            float4 bv1 = *(float4*)&Bs[k * 132 + tx * 8 + 4];
            float am[8] = {av0.x, av0.y, av0.z, av0.w, av1.x, av1.y, av1.z, av1.w};
            float bn[8] = {bv0.x, bv0.y, bv0.z, bv0.w, bv1.x, bv1.y, bv1.z, bv1.w};
#pragma unroll
            for (int i = 0; i < 8; i++)
#pragma unroll
                for (int j = 0; j < 8; j++)
                    acc[i][j] = fmaf(am[i], bn[j], acc[i][j]);
        }
    }

    const int colIn = wrow0 + tx * 8;
    float4 bia = *(const float4*)&Bias[colIn];
    float4 bib = *(const float4*)&Bias[colIn + 4];
#pragma unroll
    for (int i = 0; i < 8; i++) {
        float4 oa, ob;
        oa.x = acc[i][0] + bia.x; oa.y = acc[i][1] + bia.y;
        oa.z = acc[i][2] + bia.z; oa.w = acc[i][3] + bia.w;
        ob.x = acc[i][4] + bib.x; ob.y = acc[i][5] + bib.y;
        ob.z = acc[i][6] + bib.z; ob.w = acc[i][7] + bib.w;
        *(float4*)&Cout[(size_t)(m0 + ty * 8 + i) * 256 + colIn] = oa;
        *(float4*)&Cout[(size_t)(m0 + ty * 8 + i) * 256 + colIn + 4] = ob;
    }
}

// ---------------- K2: p_r1 = (p[idx]-p) @ wp1^T + bp1, store + BN_p stats -------
__global__ __launch_bounds__(256) void k_pr1(
    const float* __restrict__ p, const int* __restrict__ idx,
    const float* __restrict__ wp1, const float* __restrict__ bp1)
{
    const int tid = threadIdx.x;
    const int base = blockIdx.x * 1024 + tid;
    float W[9], B[3];
#pragma unroll
    for (int i = 0; i < 9; i++) W[i] = wp1[i];
#pragma unroll
    for (int i = 0; i < 3; i++) B[i] = bp1[i];

    float v6[6] = {0, 0, 0, 0, 0, 0};
#pragma unroll
    for (int it = 0; it < 4; it++) {
        int i = base + it * 256;
        int n = i >> 4;
        int j = idx[i];
        float dx = p[j * 3 + 0] - p[n * 3 + 0];
        float dy = p[j * 3 + 1] - p[n * 3 + 1];
        float dz = p[j * 3 + 2] - p[n * 3 + 2];
        float r0 = fmaf(W[0], dx, fmaf(W[1], dy, fmaf(W[2], dz, B[0])));
        float r1 = fmaf(W[3], dx, fmaf(W[4], dy, fmaf(W[5], dz, B[1])));
        float r2 = fmaf(W[6], dx, fmaf(W[7], dy, fmaf(W[8], dz, B[2])));
        g_pr1[(size_t)i * 3 + 0] = r0;
        g_pr1[(size_t)i * 3 + 1] = r1;
        g_pr1[(size_t)i * 3 + 2] = r2;
        v6[0] += r0; v6[1] += r1; v6[2] += r2;
        v6[3] = fmaf(r0, r0, v6[3]);
        v6[4] = fmaf(r1, r1, v6[4]);
        v6[5] = fmaf(r2, r2, v6[5]);
    }
#pragma unroll
    for (int i = 0; i < 6; i++)
        for (int off = 16; off; off >>= 1)
            v6[i] += __shfl_down_sync(0xffffffffu, v6[i], off);

    __shared__ float wsum[8][6];
    int warp = tid >> 5, lane = tid & 31;
    if (lane == 0)
#pragma unroll
        for (int i = 0; i < 6; i++) wsum[warp][i] = v6[i];
    __syncthreads();
    if (tid < 6) {
        float tot = 0;
#pragma unroll
        for (int w = 0; w < 8; w++) tot += wsum[w][tid];
        atomicAdd(&g_sp[tid], (double)tot);
    }
}

// ---------------- K3: BN_1 stats on w0 = xk_g - xq + p_r2 (recomputed) ----------
__global__ __launch_bounds__(256) void k_bn1(
    const int* __restrict__ idx,
    const float* __restrict__ wp2, const float* __restrict__ bp2,
    const float* __restrict__ gp, const float* __restrict__ btp)
{
    __shared__ int sidx[512];
    __shared__ float st[1536];
    __shared__ float sap[3], sdp[3];
    const int tid = threadIdx.x;
    const int n0 = blockIdx.x * 32;

    if (tid < 3) {
        double m = g_sp[tid] * INVN;
        double v = g_sp[3 + tid] * INVN - m * m;
        float a = (float)((double)gp[tid] / sqrt(v + 1e-5));
        sap[tid] = a; sdp[tid] = btp[tid] - (float)m * a;
    }
    for (int i = tid; i < 512; i += 256) sidx[i] = idx[n0 * 16 + i];
    for (int i = tid; i < 1536; i += 256) st[i] = g_pr1[(size_t)n0 * 48 + i];
    __syncthreads();
    for (int i = tid; i < 1536; i += 256) {
        int k = i % 3;
        st[i] = fmaxf(fmaf(sap[k], st[i], sdp[k]), 0.f);
    }
    const int c = tid;
    const float w0c = wp2[c * 3], w1c = wp2[c * 3 + 1], w2c = wp2[c * 3 + 2];
    const float bpc = bp2[c];
    float s = 0.f, q = 0.f;
    __syncthreads();

    for (int pt = 0; pt < 32; pt++) {
        float xqc = g_xq[(size_t)(n0 + pt) * 256 + c];
        int b16 = pt * 16;
#pragma unroll 4
        for (int ns = 0; ns < 16; ns++) {
            int j = sidx[b16 + ns];
            float t0 = st[(b16 + ns) * 3], t1 = st[(b16 + ns) * 3 + 1], t2 = st[(b16 + ns) * 3 + 2];
            float pr2 = fmaf(t0, w0c, fmaf(t1, w1c, fmaf(t2, w2c, bpc)));
            float w = g_xk[(size_t)j * 256 + c] - xqc + pr2;
            s += w;
            q = fmaf(w, w, q);
        }
    }
    atomicAdd(&g_s1[c], (double)s);
    atomicAdd(&g_s1[256 + c], (double)q);
}

// ---------------- K4: h1 = relu(bn1(w0)) @ ww1^T + bw1 (stored) + BN_2 stats ----
// 4 points/block (64 rows); ~101 KB dyn smem -> 2 blocks/SM for gather/GEMM overlap.
#define H1_SMEM ((64*260 + 32*260 + 192) * 4 + 64 * 4)
__global__ __launch_bounds__(256, 2) void k_h1(
    const int* __restrict__ idx,
    const float* __restrict__ wp2, const float* __restrict__ bp2,
    const float* __restrict__ ww1, const float* __restrict__ bw1,
    const float* __restrict__ gp, const float* __restrict__ btp,
    const float* __restrict__ g1, const float* __restrict__ b1)
{
    extern __shared__ float sm[];
    float* u_t  = sm;                 // [64][260]
    float* ww1s = sm + 64 * 260;      // [32][260]
    float* st   = ww1s + 32 * 260;    // [192]
    int*   sidx = (int*)(st + 192);   // [64]
    __shared__ float ssum[32], ssq[32];
    __shared__ float sap[3], sdp[3];

    const int tid = threadIdx.x;
    const int n0 = blockIdx.x * 4;
    const int r0g = blockIdx.x * 64;

    if (tid < 3) {
        double m = g_sp[tid] * INVN;
        double v = g_sp[3 + tid] * INVN - m * m;
        float a = (float)((double)gp[tid] / sqrt(v + 1e-5));
        sap[tid] = a; sdp[tid] = btp[tid] - (float)m * a;
    }
    if (tid < 64) sidx[tid] = idx[r0g + tid];
    if (tid < 32) { ssum[tid] = 0.f; ssq[tid] = 0.f; }
    if (tid < 192) st[tid] = g_pr1[(size_t)n0 * 48 + tid];
#pragma unroll
    for (int i = 0; i < 32; i++) ww1s[i * 260 + tid] = ww1[i * 256 + tid];

    const int c = tid;
    float a1c, d1c;
    {
        double m = g_s1[c] * INVN;
        double v = g_s1[256 + c] * INVN - m * m;
        a1c = (float)((double)g1[c] / sqrt(v + 1e-5));
        d1c = b1[c] - (float)m * a1c;
    }
    float xqr[4];
#pragma unroll
    for (int pt = 0; pt < 4; pt++) xqr[pt] = g_xq[(size_t)(n0 + pt) * 256 + c];
    const float w0c = wp2[c * 3], w1c = wp2[c * 3 + 1], w2c = wp2[c * 3 + 2];
    const float bpc = bp2[c];
    __syncthreads();

    if (tid < 192) {
        int k = tid % 3;
        st[tid] = fmaxf(fmaf(sap[k], st[tid], sdp[k]), 0.f);
    }
    __syncthreads();

    // phase 1: u[r][c] = relu(bn1(xk_g - xq + pr2))
#pragma unroll 4
    for (int r = 0; r < 64; r++) {
        int j = sidx[r];
        float t0 = st[r * 3], t1 = st[r * 3 + 1], t2 = st[r * 3 + 2];
        float pr2 = fmaf(t0, w0c, fmaf(t1, w1c, fmaf(t2, w2c, bpc)));
        float w = g_xk[(size_t)j * 256 + c] - xqr[r >> 4] + pr2;
        u_t[r * 260 + c] = fmaxf(fmaf(a1c, w, d1c), 0.f);
    }
    __syncthreads();

    // phase 2: h1[64][32] = u[64][256] @ ww1^T, 4x2 microtile
    const int rr0 = (tid & 15) * 4;
    const int j0  = (tid >> 4) * 2;
    float acc[4][2];
#pragma unroll
    for (int i = 0; i < 4; i++) { acc[i][0] = 0.f; acc[i][1] = 0.f; }

    for (int k0 = 0; k0 < 256; k0 += 4) {
        float4 U[4];
#pragma unroll
        for (int i = 0; i < 4; i++) U[i] = *(float4*)&u_t[(rr0 + i) * 260 + k0];
        float4 W0 = *(float4*)&ww1s[j0 * 260 + k0];
        float4 W1 = *(float4*)&ww1s[(j0 + 1) * 260 + k0];
#pragma unroll
        for (int i = 0; i < 4; i++) {
            acc[i][0] = fmaf(U[i].x, W0.x, acc[i][0]);
            acc[i][0] = fmaf(U[i].y, W0.y, acc[i][0]);
            acc[i][0] = fmaf(U[i].z, W0.z, acc[i][0]);
            acc[i][0] = fmaf(U[i].w, W0.w, acc[i][0]);
            acc[i][1] = fmaf(U[i].x, W1.x, acc[i][1]);
            acc[i][1] = fmaf(U[i].y, W1.y, acc[i][1]);
            acc[i][1] = fmaf(U[i].z, W1.z, acc[i][1]);
            acc[i][1] = fmaf(U[i].w, W1.w, acc[i][1]);
        }
    }

    float bwa = bw1[j0], bwb = bw1[j0 + 1];
    float cs0 = 0.f, cq0 = 0.f, cs1 = 0.f, cq1 = 0.f;
#pragma unroll
    for (int i = 0; i < 4; i++) {
        float2 o;
        o.x = acc[i][0] + bwa;
        o.y = acc[i][1] + bwb;
        *(float2*)&g_h1[(size_t)(r0g + rr0 + i) * 32 + j0] = o;
        cs0 += o.x; cq0 = fmaf(o.x, o.x, cq0);
        cs1 += o.y; cq1 = fmaf(o.y, o.y, cq1);
    }
    atomicAdd(&ssum[j0], cs0);
    atomicAdd(&ssq[j0], cq0);
    atomicAdd(&ssum[j0 + 1], cs1);
    atomicAdd(&ssq[j0 + 1], cq1);
    __syncthreads();
    if (tid < 32) {
        atomicAdd(&g_s2[tid], (double)ssum[tid]);
        atomicAdd(&g_s2[32 + tid], (double)ssq[tid]);
    }
}

// ---------------- K5: bn2+relu -> @ww2 -> softmax(ns) -> weighted gather-sum ----
// 4 points per block.
__global__ __launch_bounds__(256) void k_out(
    const int* __restrict__ idx,
    const float* __restrict__ wp2, const float* __restrict__ bp2,
    const float* __restrict__ ww2, const float* __restrict__ bw2,
    const float* __restrict__ gp, const float* __restrict__ btp,
    const float* __restrict__ g2, const float* __restrict__ b2,
    float* __restrict__ out)
{
    __shared__ int sidx[64];
    __shared__ float st[192];
    __shared__ float sv[2048];          // [pt][ns][k] bn2-relu'd h1
    __shared__ float sw2t[32 * 36];     // [j][k] transposed ww2
    __shared__ float sh[4 * 528];       // [pt][ns*33 + k] logits/softmax
    __shared__ float sbw[32];
    __shared__ float sa2[32], sd2[32];
    __shared__ float sap[3], sdp[3];

    const int tid = threadIdx.x;
    const int n0 = blockIdx.x * 4;

    if (tid < 3) {
        double m = g_sp[tid] * INVN;
        double v = g_sp[3 + tid] * INVN - m * m;
        float a = (float)((double)gp[tid] / sqrt(v + 1e-5));
        sap[tid] = a; sdp[tid] = btp[tid] - (float)m * a;
    }
    if (tid >= 32 && tid < 64) {
        int k = tid - 32;
        double m = g_s2[k] * INVN;
        double v = g_s2[32 + k] * INVN - m * m;
        float a = (float)((double)g2[k] / sqrt(v + 1e-5));
        sa2[k] = a; sd2[k] = b2[k] - (float)m * a;
    }
    if (tid < 64) sidx[tid] = idx[n0 * 16 + tid];
    if (tid >= 64 && tid < 96) sbw[tid - 64] = bw2[tid - 64];
    for (int f = tid; f < 1024; f += 256) sw2t[(f & 31) * 36 + (f >> 5)] = ww2[f];
    __syncthreads();

    if (tid < 192) {
        int k = tid % 3;
        float v = g_pr1[(size_t)n0 * 48 + tid];
        st[tid] = fmaxf(fmaf(sap[k], v, sdp[k]), 0.f);
    }
#pragma unroll
    for (int rep = 0; rep < 8; rep++) {
        int i = tid + rep * 256;
        int k = i & 31;
        float hv = g_h1[(size_t)n0 * 512 + i];
        sv[i] = fmaxf(fmaf(sa2[k], hv, sd2[k]), 0.f);
    }
    __syncthreads();

    // logits: thread -> (pt,ns) pair + 8 output channels
    {
        const int pair = tid >> 2;                 // 0..63 = pt*16+ns
        const int kq = (tid & 3) * 8;
        float a[8];
        float4 bwa = *(float4*)&sbw[kq];
        float4 bwb = *(float4*)&sbw[kq + 4];
        a[0] = bwa.x; a[1] = bwa.y; a[2] = bwa.z; a[3] = bwa.w;
        a[4] = bwb.x; a[5] = bwb.y; a[6] = bwb.z; a[7] = bwb.w;
#pragma unroll 4
        for (int j = 0; j < 32; j++) {
            float s = sv[pair * 32 + j];
            float4 w0 = *(float4*)&sw2t[j * 36 + kq];
            float4 w1 = *(float4*)&sw2t[j * 36 + kq + 4];
            a[0] = fmaf(s, w0.x, a[0]); a[1] = fmaf(s, w0.y, a[1]);
            a[2] = fmaf(s, w0.z, a[2]); a[3] = fmaf(s, w0.w, a[3]);
            a[4] = fmaf(s, w1.x, a[4]); a[5] = fmaf(s, w1.y, a[5]);
            a[6] = fmaf(s, w1.z, a[6]); a[7] = fmaf(s, w1.w, a[7]);
        }
        int pt = pair >> 4, ns = pair & 15;
#pragma unroll
        for (int r = 0; r < 8; r++) sh[pt * 528 + ns * 33 + kq + r] = a[r];
    }
    __syncthreads();

    // softmax over ns (16) for each (pt, k)
    if (tid < 128) {
        int pt = tid >> 5, k = tid & 31;
        float* row = &sh[pt * 528 + k];
        float m = -1e30f;
#pragma unroll
        for (int ns = 0; ns < 16; ns++) m = fmaxf(m, row[ns * 33]);
        float s = 0.f;
#pragma unroll
        for (int ns = 0; ns < 16; ns++) {
            float e = expf(row[ns * 33] - m);
            row[ns * 33] = e;
            s += e;
        }
        float inv = 1.f / s;
#pragma unroll
        for (int ns = 0; ns < 16; ns++) row[ns * 33] *= inv;
    }
    __syncthreads();

    // weighted gather-sum
    const int c = tid;
    const float w0c = wp2[c * 3], w1c = wp2[c * 3 + 1], w2c = wp2[c * 3 + 2];
    const float bpc = bp2[c];
    const int jl = c & 31;
#pragma unroll
    for (int pt = 0; pt < 4; pt++) {
        float a = 0.f;
#pragma unroll 4
        for (int ns = 0; ns < 16; ns++) {
            int r = pt * 16 + ns;
            int j = sidx[r];
            float t0 = st[r * 3], t1 = st[r * 3 + 1], t2 = st[r * 3 + 2];
            float pr2 = fmaf(t0, w0c, fmaf(t1, w1c, fmaf(t2, w2c, bpc)));
            a = fmaf(g_xv[(size_t)j * 256 + c] + pr2, sh[pt * 528 + ns * 33 + jl], a);
        }
        out[(size_t)(n0 + pt) * 256 + c] = a;
    }
}

// ---------------- launch ----------------
extern "C" void kernel_launch(void* const* d_in, const int* in_sizes, int n_in,
                              void* d_out, int out_size)
{
    (void)in_sizes; (void)n_in; (void)out_size;
    const float* p   = (const float*)d_in[0];
    const float* x   = (const float*)d_in[1];
    const int*   idx = (const int*)  d_in[2];
    const float* wq  = (const float*)d_in[3];
    const float* bq  = (const float*)d_in[4];
    const float* wk  = (const float*)d_in[5];
    const float* bk  = (const float*)d_in[6];
    const float* wv  = (const float*)d_in[7];
    const float* bv  = (const float*)d_in[8];
    const float* wp1 = (const float*)d_in[9];
    const float* bp1 = (const float*)d_in[10];
    const float* gp  = (const float*)d_in[11];
    const float* btp = (const float*)d_in[12];
    const float* wp2 = (const float*)d_in[13];
    const float* bp2 = (const float*)d_in[14];
    const float* g1  = (const float*)d_in[15];
    const float* b1  = (const float*)d_in[16];
    const float* ww1 = (const float*)d_in[17];
    const float* bw1 = (const float*)d_in[18];
    const float* g2  = (const float*)d_in[19];
    const float* b2  = (const float*)d_in[20];
    const float* ww2 = (const float*)d_in[21];
    const float* bw2 = (const float*)d_in[22];
    float* out = (float*)d_out;

    cudaFuncSetAttribute(k_h1, cudaFuncAttributeMaxDynamicSharedMemorySize, H1_SMEM);

    k_zero<<<1, 256>>>();
    k_qkv<<<dim3(6, 512), 256>>>(x, wq, bq, wk, bk, wv, bv);
    k_pr1<<<1024, 256>>>(p, idx, wp1, bp1);
    k_bn1<<<2048, 256>>>(idx, wp2, bp2, gp, btp);
    k_h1<<<16384, 256, H1_SMEM>>>(idx, wp2, bp2, ww1, bw1, gp, btp, g1, b1);
    k_out<<<16384, 256>>>(idx, wp2, bp2, ww2, bw2, gp, btp, g2, b2, out);
}

// round 9
// speedup vs baseline: 1.9239x; 1.9167x over previous
#include <cuda_runtime.h>
#include <cuda_bf16.h>
#include <stdint.h>
#include <math.h>

#define NPTS   65536
#define NSAMP  16
#define CDIM   256
#define CH2    32
#define NROWS  (NPTS*NSAMP)   // 1048576
#define INVN   (1.0/(double)NROWS)

// ---------------- device scratch (static; no allocation allowed) ----------------
__device__ float g_xq[NPTS*CDIM];              // 64 MB
__device__ float g_xk[NPTS*CDIM];              // 64 MB
__device__ float g_xv[NPTS*CDIM];              // 64 MB
__device__ __nv_bfloat16 g_xh[NPTS*CDIM];      // 32 MB split-bf16 of x
__device__ __nv_bfloat16 g_xl[NPTS*CDIM];      // 32 MB
__device__ __nv_bfloat16 g_wh[768*CDIM];       // stacked [wq;wk;wv] hi
__device__ __nv_bfloat16 g_wl[768*CDIM];       // lo
__device__ __nv_bfloat16 g_w1h[CH2*CDIM];      // ww1 hi
__device__ __nv_bfloat16 g_w1l[CH2*CDIM];      // ww1 lo
__device__ float g_pr1[NROWS*3];               // 12 MB
__device__ float g_h1[NROWS*CH2];              // 128 MB
__device__ double g_sp[6];
__device__ double g_s1[512];
__device__ double g_s2[64];

// ---------------- mma helpers ----------------
__device__ __forceinline__ uint32_t smaddr(const void* p) {
    return (uint32_t)__cvta_generic_to_shared(p);
}
__device__ __forceinline__ void ldsm4(uint32_t a, uint32_t& r0, uint32_t& r1, uint32_t& r2, uint32_t& r3) {
    asm volatile("ldmatrix.sync.aligned.m8n8.x4.shared.b16 {%0,%1,%2,%3}, [%4];"
                 : "=r"(r0), "=r"(r1), "=r"(r2), "=r"(r3) : "r"(a));
}
__device__ __forceinline__ void ldsm2(uint32_t a, uint32_t& r0, uint32_t& r1) {
    asm volatile("ldmatrix.sync.aligned.m8n8.x2.shared.b16 {%0,%1}, [%2];"
                 : "=r"(r0), "=r"(r1) : "r"(a));
}
__device__ __forceinline__ void mma16816(float* c, const uint32_t* a, const uint32_t* b) {
    asm volatile("mma.sync.aligned.m16n8k16.row.col.f32.bf16.bf16.f32 "
                 "{%0,%1,%2,%3},{%4,%5,%6,%7},{%8,%9},{%0,%1,%2,%3};"
                 : "+f"(c[0]), "+f"(c[1]), "+f"(c[2]), "+f"(c[3])
                 : "r"(a[0]), "r"(a[1]), "r"(a[2]), "r"(a[3]), "r"(b[0]), "r"(b[1]));
}

// ---------------- K0: zero stat accumulators ----------------
__global__ void k_zero() {
    int t = threadIdx.x;
    if (t < 6) g_sp[t] = 0.0;
    for (int i = t; i < 512; i += 256) g_s1[i] = 0.0;
    if (t < 64) g_s2[t] = 0.0;
}

// ---------------- K_cvt: split-bf16 conversion of x, [wq;wk;wv], ww1 ----------
__global__ __launch_bounds__(256) void k_cvt(
    const float* __restrict__ x,
    const float* __restrict__ wq, const float* __restrict__ wk, const float* __restrict__ wv,
    const float* __restrict__ ww1)
{
    const int b = blockIdx.x, tid = threadIdx.x;
    const float* src;
    __nv_bfloat16 *dh, *dl;
    size_t off;
    if (b < 4096) {
        off = (size_t)b * 4096 + (size_t)tid * 16;
        src = x + off; dh = g_xh; dl = g_xl;
    } else if (b < 4144) {
        size_t i = (size_t)(b - 4096) * 4096 + (size_t)tid * 16;  // 0..196607
        off = i;
        int row = (int)(i >> 8);
        const float* w = (row < 256) ? wq : (row < 512) ? wk : wv;
        src = w + (size_t)(row & 255) * 256 + (i & 255);
        dh = g_wh; dl = g_wl;
    } else {
        size_t i = (size_t)(b - 4144) * 4096 + (size_t)tid * 16;  // 0..8191
        off = i; src = ww1 + i; dh = g_w1h; dl = g_w1l;
    }
#pragma unroll
    for (int j = 0; j < 4; j++) {
        float4 v = *(const float4*)(src + j * 4);
        __nv_bfloat16 h0 = __float2bfloat16(v.x);
        __nv_bfloat16 h1 = __float2bfloat16(v.y);
        __nv_bfloat16 h2 = __float2bfloat16(v.z);
        __nv_bfloat16 h3 = __float2bfloat16(v.w);
        __nv_bfloat16 l0 = __float2bfloat16(v.x - __bfloat162float(h0));
        __nv_bfloat16 l1 = __float2bfloat16(v.y - __bfloat162float(h1));
        __nv_bfloat16 l2 = __float2bfloat16(v.z - __bfloat162float(h2));
        __nv_bfloat16 l3 = __float2bfloat16(v.w - __bfloat162float(h3));
        *(__nv_bfloat162*)(dh + off + j * 4)     = __nv_bfloat162(h0, h1);
        *(__nv_bfloat162*)(dh + off + j * 4 + 2) = __nv_bfloat162(h2, h3);
        *(__nv_bfloat162*)(dl + off + j * 4)     = __nv_bfloat162(l0, l1);
        *(__nv_bfloat162*)(dl + off + j * 4 + 2) = __nv_bfloat162(l2, l3);
    }
}

// ---------------- K1: QKV via split-bf16 tensor-core GEMM ----------------
// C[65536,768] = x @ W^T + b.  Block tile 128x128, 8 warps (2x4), warp tile 64x32.
#define QS 72
#define QKV_SMEM (4*128*QS*2)   // 73728 B
__global__ __launch_bounds__(256, 2) void k_qkv_mma(
    const float* __restrict__ bq, const float* __restrict__ bk, const float* __restrict__ bv)
{
    extern __shared__ __nv_bfloat16 qs[];
    __nv_bfloat16* Ah = qs;
    __nv_bfloat16* Al = Ah + 128 * QS;
    __nv_bfloat16* Bh = Al + 128 * QS;
    __nv_bfloat16* Bl = Bh + 128 * QS;

    const int tid = threadIdx.x, wid = tid >> 5, lane = tid & 31;
    const int bx = blockIdx.x;
    const int m0 = blockIdx.y * 128;
    const int n0 = bx * 128;
    const int mw = wid & 1, nw = wid >> 1;

    float c[4][4][4];
#pragma unroll
    for (int i = 0; i < 4; i++)
#pragma unroll
        for (int j = 0; j < 4; j++)
#pragma unroll
            for (int r = 0; r < 4; r++) c[i][j][r] = 0.f;

    const int ldr = tid >> 3, ldc = tid & 7;
    const uint32_t aBaseH = smaddr(Ah), aBaseL = smaddr(Al);
    const uint32_t bBaseH = smaddr(Bh), bBaseL = smaddr(Bl);
    const int agrp = lane >> 3, ar = lane & 7;
    const int aRowOff = (agrp & 1) * 8 + ar;
    const int aColOff = (agrp >> 1) * 8;
    const int br = lane & 7, bg = (lane >> 3) & 1;

    for (int kc = 0; kc < 4; kc++) {
        const int kbase = kc * 64;
        __syncthreads();
#pragma unroll
        for (int i = 0; i < 4; i++) {
            int row = ldr + i * 32;
            size_t gA = (size_t)(m0 + row) * 256 + kbase + ldc * 8;
            size_t gB = (size_t)(n0 + row) * 256 + kbase + ldc * 8;
            *(uint4*)&Ah[row * QS + ldc * 8] = *(const uint4*)&g_xh[gA];
            *(uint4*)&Al[row * QS + ldc * 8] = *(const uint4*)&g_xl[gA];
            *(uint4*)&Bh[row * QS + ldc * 8] = *(const uint4*)&g_wh[gB];
            *(uint4*)&Bl[row * QS + ldc * 8] = *(const uint4*)&g_wl[gB];
        }
        __syncthreads();
#pragma unroll
        for (int ks = 0; ks < 4; ks++) {
            const int k0 = ks * 16;
            uint32_t bh[4][2], bl[4][2];
#pragma unroll
            for (int nt = 0; nt < 4; nt++) {
                int rowB = nw * 32 + nt * 8 + br;
                uint32_t off = (uint32_t)((rowB * QS + k0 + bg * 8) * 2);
                ldsm2(bBaseH + off, bh[nt][0], bh[nt][1]);
                ldsm2(bBaseL + off, bl[nt][0], bl[nt][1]);
            }
#pragma unroll
            for (int mt = 0; mt < 4; mt++) {
                int rowA = mw * 64 + mt * 16 + aRowOff;
                uint32_t off = (uint32_t)((rowA * QS + k0 + aColOff) * 2);
                uint32_t ah[4], al[4];
                ldsm4(aBaseH + off, ah[0], ah[1], ah[2], ah[3]);
                ldsm4(aBaseL + off, al[0], al[1], al[2], al[3]);
#pragma unroll
                for (int nt = 0; nt < 4; nt++) {
                    mma16816(c[mt][nt], ah, bh[nt]);
                    mma16816(c[mt][nt], ah, bl[nt]);
                    mma16816(c[mt][nt], al, bh[nt]);
                }
            }
        }
    }

    const int buf = bx >> 1;
    float* Cout = (buf == 0) ? g_xq : (buf == 1) ? g_xk : g_xv;
    const float* Bias = (buf == 0) ? bq : (buf == 1) ? bk : bv;
    const int gr = lane >> 2, gc = lane & 3;
#pragma unroll
    for (int mt = 0; mt < 4; mt++) {
        int row = m0 + mw * 64 + mt * 16 + gr;
#pragma unroll
        for (int nt = 0; nt < 4; nt++) {
            int colg = (bx & 1) * 128 + nw * 32 + nt * 8 + gc * 2;
            float b0 = Bias[colg], b1 = Bias[colg + 1];
            *(float2*)&Cout[(size_t)row * 256 + colg] =
                make_float2(c[mt][nt][0] + b0, c[mt][nt][1] + b1);
            *(float2*)&Cout[(size_t)(row + 8) * 256 + colg] =
                make_float2(c[mt][nt][2] + b0, c[mt][nt][3] + b1);
        }
    }
}

// ---------------- K2: p_r1 + BN_p stats ----------------
__global__ __launch_bounds__(256) void k_pr1(
    const float* __restrict__ p, const int* __restrict__ idx,
    const float* __restrict__ wp1, const float* __restrict__ bp1)
{
    const int tid = threadIdx.x;
    const int base = blockIdx.x * 1024 + tid;
    float W[9], B[3];
#pragma unroll
    for (int i = 0; i < 9; i++) W[i] = wp1[i];
#pragma unroll
    for (int i = 0; i < 3; i++) B[i] = bp1[i];

    float v6[6] = {0, 0, 0, 0, 0, 0};
#pragma unroll
    for (int it = 0; it < 4; it++) {
        int i = base + it * 256;
        int n = i >> 4;
        int j = idx[i];
        float dx = p[j * 3 + 0] - p[n * 3 + 0];
        float dy = p[j * 3 + 1] - p[n * 3 + 1];
        float dz = p[j * 3 + 2] - p[n * 3 + 2];
        float r0 = fmaf(W[0], dx, fmaf(W[1], dy, fmaf(W[2], dz, B[0])));
        float r1 = fmaf(W[3], dx, fmaf(W[4], dy, fmaf(W[5], dz, B[1])));
        float r2 = fmaf(W[6], dx, fmaf(W[7], dy, fmaf(W[8], dz, B[2])));
        g_pr1[(size_t)i * 3 + 0] = r0;
        g_pr1[(size_t)i * 3 + 1] = r1;
        g_pr1[(size_t)i * 3 + 2] = r2;
        v6[0] += r0; v6[1] += r1; v6[2] += r2;
        v6[3] = fmaf(r0, r0, v6[3]);
        v6[4] = fmaf(r1, r1, v6[4]);
        v6[5] = fmaf(r2, r2, v6[5]);
    }
#pragma unroll
    for (int i = 0; i < 6; i++)
        for (int off = 16; off; off >>= 1)
            v6[i] += __shfl_down_sync(0xffffffffu, v6[i], off);

    __shared__ float wsum[8][6];
    int warp = tid >> 5, lane = tid & 31;
    if (lane == 0)
#pragma unroll
        for (int i = 0; i < 6; i++) wsum[warp][i] = v6[i];
    __syncthreads();
    if (tid < 6) {
        float tot = 0;
#pragma unroll
        for (int w = 0; w < 8; w++) tot += wsum[w][tid];
        atomicAdd(&g_sp[tid], (double)tot);
    }
}

// ---------------- K3: BN_1 stats ----------------
__global__ __launch_bounds__(256) void k_bn1(
    const int* __restrict__ idx,
    const float* __restrict__ wp2, const float* __restrict__ bp2,
    const float* __restrict__ gp, const float* __restrict__ btp)
{
    __shared__ int sidx[512];
    __shared__ float st[1536];
    __shared__ float sap[3], sdp[3];
    const int tid = threadIdx.x;
    const int n0 = blockIdx.x * 32;

    if (tid < 3) {
        double m = g_sp[tid] * INVN;
        double v = g_sp[3 + tid] * INVN - m * m;
        float a = (float)((double)gp[tid] / sqrt(v + 1e-5));
        sap[tid] = a; sdp[tid] = btp[tid] - (float)m * a;
    }
    for (int i = tid; i < 512; i += 256) sidx[i] = idx[n0 * 16 + i];
    for (int i = tid; i < 1536; i += 256) st[i] = g_pr1[(size_t)n0 * 48 + i];
    __syncthreads();
    for (int i = tid; i < 1536; i += 256) {
        int k = i % 3;
        st[i] = fmaxf(fmaf(sap[k], st[i], sdp[k]), 0.f);
    }
    const int c = tid;
    const float w0c = wp2[c * 3], w1c = wp2[c * 3 + 1], w2c = wp2[c * 3 + 2];
    const float bpc = bp2[c];
    float s = 0.f, q = 0.f;
    __syncthreads();

    for (int pt = 0; pt < 32; pt++) {
        float xqc = g_xq[(size_t)(n0 + pt) * 256 + c];
        int b16 = pt * 16;
#pragma unroll 4
        for (int ns = 0; ns < 16; ns++) {
            int j = sidx[b16 + ns];
            float t0 = st[(b16 + ns) * 3], t1 = st[(b16 + ns) * 3 + 1], t2 = st[(b16 + ns) * 3 + 2];
            float pr2 = fmaf(t0, w0c, fmaf(t1, w1c, fmaf(t2, w2c, bpc)));
            float w = g_xk[(size_t)j * 256 + c] - xqc + pr2;
            s += w;
            q = fmaf(w, w, q);
        }
    }
    atomicAdd(&g_s1[c], (double)s);
    atomicAdd(&g_s1[256 + c], (double)q);
}

// ---------------- K4: h1 via gather + split-bf16 tensor-core GEMM ---------------
// 4 points/block (64 rows). u staged as bf16 hi/lo in smem; 8 mma warps:
// warp w handles m-tile (w&3), K-half (w>>2); partials combined in fp32 smem.
#define HS 264
#define H1_SMEM ((192*HS)*2 + 64*36*4)   // 101376 + 9216 = 110592 B
__global__ __launch_bounds__(256, 2) void k_h1(
    const int* __restrict__ idx,
    const float* __restrict__ wp2, const float* __restrict__ bp2,
    const float* __restrict__ bw1,
    const float* __restrict__ gp, const float* __restrict__ btp,
    const float* __restrict__ g1, const float* __restrict__ b1)
{
    extern __shared__ __nv_bfloat16 hsm[];
    __nv_bfloat16* uh = hsm;                  // [64][HS]
    __nv_bfloat16* ul = uh + 64 * HS;
    __nv_bfloat16* wh = ul + 64 * HS;         // [32][HS]
    __nv_bfloat16* wl = wh + 32 * HS;
    float* Ctmp = (float*)(wl + 32 * HS);     // [64][36]
    __shared__ int sidx[64];
    __shared__ float st[192];
    __shared__ float ssum[32], ssq[32];
    __shared__ float sap[3], sdp[3];

    const int tid = threadIdx.x, wid = tid >> 5, lane = tid & 31;
    const int n0 = blockIdx.x * 4;
    const int r0g = blockIdx.x * 64;

    if (tid < 3) {
        double m = g_sp[tid] * INVN;
        double v = g_sp[3 + tid] * INVN - m * m;
        float a = (float)((double)gp[tid] / sqrt(v + 1e-5));
        sap[tid] = a; sdp[tid] = btp[tid] - (float)m * a;
    }
    if (tid < 64) sidx[tid] = idx[r0g + tid];
    if (tid < 32) { ssum[tid] = 0.f; ssq[tid] = 0.f; }
    if (tid < 192) st[tid] = g_pr1[(size_t)n0 * 48 + tid];
#pragma unroll
    for (int i = 0; i < 4; i++) {
        int id = tid + i * 256;
        int row = id >> 5, col8 = id & 31;
        *(uint4*)&wh[row * HS + col8 * 8] = *(const uint4*)&g_w1h[row * 256 + col8 * 8];
        *(uint4*)&wl[row * HS + col8 * 8] = *(const uint4*)&g_w1l[row * 256 + col8 * 8];
    }

    const int c = tid;
    float a1c, d1c;
    {
        double m = g_s1[c] * INVN;
        double v = g_s1[256 + c] * INVN - m * m;
        a1c = (float)((double)g1[c] / sqrt(v + 1e-5));
        d1c = b1[c] - (float)m * a1c;
    }
    float xqr[4];
#pragma unroll
    for (int pt = 0; pt < 4; pt++) xqr[pt] = g_xq[(size_t)(n0 + pt) * 256 + c];
    const float w0c = wp2[c * 3], w1c = wp2[c * 3 + 1], w2c = wp2[c * 3 + 2];
    const float bpc = bp2[c];
    __syncthreads();

    if (tid < 192) {
        int k = tid % 3;
        st[tid] = fmaxf(fmaf(sap[k], st[tid], sdp[k]), 0.f);
    }
    __syncthreads();

    // phase 1: gather + bn1 + relu -> split bf16 into smem
#pragma unroll 4
    for (int r = 0; r < 64; r++) {
        int j = sidx[r];
        float t0 = st[r * 3], t1 = st[r * 3 + 1], t2 = st[r * 3 + 2];
        float pr2 = fmaf(t0, w0c, fmaf(t1, w1c, fmaf(t2, w2c, bpc)));
        float w = g_xk[(size_t)j * 256 + c] - xqr[r >> 4] + pr2;
        float u = fmaxf(fmaf(a1c, w, d1c), 0.f);
        __nv_bfloat16 h = __float2bfloat16(u);
        uh[r * HS + c] = h;
        ul[r * HS + c] = __float2bfloat16(u - __bfloat162float(h));
    }
    __syncthreads();

    // phase 2: C[64][32] = u @ ww1^T via mma
    const int mt = wid & 3, kh = wid >> 2;
    float c4[4][4];
#pragma unroll
    for (int nt = 0; nt < 4; nt++)
#pragma unroll
        for (int r = 0; r < 4; r++) c4[nt][r] = 0.f;

    const uint32_t uBaseH = smaddr(uh), uBaseL = smaddr(ul);
    const uint32_t wBaseH = smaddr(wh), wBaseL = smaddr(wl);
    const int agrp = lane >> 3, ar = lane & 7;
    const int aRowOff = (agrp & 1) * 8 + ar;
    const int aColOff = (agrp >> 1) * 8;
    const int br = lane & 7, bg = (lane >> 3) & 1;

#pragma unroll
    for (int ks = 0; ks < 8; ks++) {
        const int k0 = kh * 128 + ks * 16;
        uint32_t bh[4][2], bl[4][2];
#pragma unroll
        for (int nt = 0; nt < 4; nt++) {
            uint32_t off = (uint32_t)(((nt * 8 + br) * HS + k0 + bg * 8) * 2);
            ldsm2(wBaseH + off, bh[nt][0], bh[nt][1]);
            ldsm2(wBaseL + off, bl[nt][0], bl[nt][1]);
        }
        uint32_t ah[4], al[4];
        uint32_t offA = (uint32_t)(((mt * 16 + aRowOff) * HS + k0 + aColOff) * 2);
        ldsm4(uBaseH + offA, ah[0], ah[1], ah[2], ah[3]);
        ldsm4(uBaseL + offA, al[0], al[1], al[2], al[3]);
#pragma unroll
        for (int nt = 0; nt < 4; nt++) {
            mma16816(c4[nt], ah, bh[nt]);
            mma16816(c4[nt], ah, bl[nt]);
            mma16816(c4[nt], al, bh[nt]);
        }
    }

    const int gr = lane >> 2, gc = lane & 3;
    if (wid < 4) {
#pragma unroll
        for (int nt = 0; nt < 4; nt++) {
            Ctmp[(mt * 16 + gr) * 36 + nt * 8 + gc * 2]         = c4[nt][0];
            Ctmp[(mt * 16 + gr) * 36 + nt * 8 + gc * 2 + 1]     = c4[nt][1];
            Ctmp[(mt * 16 + gr + 8) * 36 + nt * 8 + gc * 2]     = c4[nt][2];
            Ctmp[(mt * 16 + gr + 8) * 36 + nt * 8 + gc * 2 + 1] = c4[nt][3];
        }
    }
    __syncthreads();
    if (wid >= 4) {
#pragma unroll
        for (int nt = 0; nt < 4; nt++) {
            Ctmp[(mt * 16 + gr) * 36 + nt * 8 + gc * 2]         += c4[nt][0];
            Ctmp[(mt * 16 + gr) * 36 + nt * 8 + gc * 2 + 1]     += c4[nt][1];
            Ctmp[(mt * 16 + gr + 8) * 36 + nt * 8 + gc * 2]     += c4[nt][2];
            Ctmp[(mt * 16 + gr + 8) * 36 + nt * 8 + gc * 2 + 1] += c4[nt][3];
        }
    }
    __syncthreads();

    // epilogue: bias, store h1 (coalesced), BN2 stats
    {
        const int col = tid & 31;
        const int rg = tid >> 5;
        const float bw = bw1[col];
        float s = 0.f, q = 0.f;
#pragma unroll
        for (int i = 0; i < 8; i++) {
            int r = rg * 8 + i;
            float v = Ctmp[r * 36 + col] + bw;
            g_h1[(size_t)(r0g + r) * 32 + col] = v;
            s += v;
            q = fmaf(v, v, q);
        }
        atomicAdd(&ssum[col], s);
        atomicAdd(&ssq[col], q);
    }
    __syncthreads();
    if (tid < 32) {
        atomicAdd(&g_s2[tid], (double)ssum[tid]);
        atomicAdd(&g_s2[32 + tid], (double)ssq[tid]);
    }
}

// ---------------- K5: bn2+relu -> @ww2 -> softmax(ns) -> weighted gather-sum ----
__global__ __launch_bounds__(256) void k_out(
    const int* __restrict__ idx,
    const float* __restrict__ wp2, const float* __restrict__ bp2,
    const float* __restrict__ ww2, const float* __restrict__ bw2,
    const float* __restrict__ gp, const float* __restrict__ btp,
    const float* __restrict__ g2, const float* __restrict__ b2,
    float* __restrict__ out)
{
    __shared__ int sidx[64];
    __shared__ float st[192];
    __shared__ float sv[2048];
    __shared__ float sw2t[32 * 36];
    __shared__ float sh[4 * 528];
    __shared__ float sbw[32];
    __shared__ float sa2[32], sd2[32];
    __shared__ float sap[3], sdp[3];

    const int tid = threadIdx.x;
    const int n0 = blockIdx.x * 4;

    if (tid < 3) {
        double m = g_sp[tid] * INVN;
        double v = g_sp[3 + tid] * INVN - m * m;
        float a = (float)((double)gp[tid] / sqrt(v + 1e-5));
        sap[tid] = a; sdp[tid] = btp[tid] - (float)m * a;
    }
    if (tid >= 32 && tid < 64) {
        int k = tid - 32;
        double m = g_s2[k] * INVN;
        double v = g_s2[32 + k] * INVN - m * m;
        float a = (float)((double)g2[k] / sqrt(v + 1e-5));
        sa2[k] = a; sd2[k] = b2[k] - (float)m * a;
    }
    if (tid < 64) sidx[tid] = idx[n0 * 16 + tid];
    if (tid >= 64 && tid < 96) sbw[tid - 64] = bw2[tid - 64];
    for (int f = tid; f < 1024; f += 256) sw2t[(f & 31) * 36 + (f >> 5)] = ww2[f];
    __syncthreads();

    if (tid < 192) {
        int k = tid % 3;
        float v = g_pr1[(size_t)n0 * 48 + tid];
        st[tid] = fmaxf(fmaf(sap[k], v, sdp[k]), 0.f);
    }
#pragma unroll
    for (int rep = 0; rep < 8; rep++) {
        int i = tid + rep * 256;
        int k = i & 31;
        float hv = g_h1[(size_t)n0 * 512 + i];
        sv[i] = fmaxf(fmaf(sa2[k], hv, sd2[k]), 0.f);
    }
    __syncthreads();

    {
        const int pair = tid >> 2;
        const int kq = (tid & 3) * 8;
        float a[8];
        float4 bwa = *(float4*)&sbw[kq];
        float4 bwb = *(float4*)&sbw[kq + 4];
        a[0] = bwa.x; a[1] = bwa.y; a[2] = bwa.z; a[3] = bwa.w;
        a[4] = bwb.x; a[5] = bwb.y; a[6] = bwb.z; a[7] = bwb.w;
#pragma unroll 4
        for (int j = 0; j < 32; j++) {
            float s = sv[pair * 32 + j];
            float4 w0 = *(float4*)&sw2t[j * 36 + kq];
            float4 w1 = *(float4*)&sw2t[j * 36 + kq + 4];
            a[0] = fmaf(s, w0.x, a[0]); a[1] = fmaf(s, w0.y, a[1]);
            a[2] = fmaf(s, w0.z, a[2]); a[3] = fmaf(s, w0.w, a[3]);
            a[4] = fmaf(s, w1.x, a[4]); a[5] = fmaf(s, w1.y, a[5]);
            a[6] = fmaf(s, w1.z, a[6]); a[7] = fmaf(s, w1.w, a[7]);
        }
        int pt = pair >> 4, ns = pair & 15;
#pragma unroll
        for (int r = 0; r < 8; r++) sh[pt * 528 + ns * 33 + kq + r] = a[r];
    }
    __syncthreads();

    if (tid < 128) {
        int pt = tid >> 5, k = tid & 31;
        float* row = &sh[pt * 528 + k];
        float m = -1e30f;
#pragma unroll
        for (int ns = 0; ns < 16; ns++) m = fmaxf(m, row[ns * 33]);
        float s = 0.f;
#pragma unroll
        for (int ns = 0; ns < 16; ns++) {
            float e = expf(row[ns * 33] - m);
            row[ns * 33] = e;
            s += e;
        }
        float inv = 1.f / s;
#pragma unroll
        for (int ns = 0; ns < 16; ns++) row[ns * 33] *= inv;
    }
    __syncthreads();

    const int c = tid;
    const float w0c = wp2[c * 3], w1c = wp2[c * 3 + 1], w2c = wp2[c * 3 + 2];
    const float bpc = bp2[c];
    const int jl = c & 31;
#pragma unroll
    for (int pt = 0; pt < 4; pt++) {
        float a = 0.f;
#pragma unroll 4
        for (int ns = 0; ns < 16; ns++) {
            int r = pt * 16 + ns;
            int j = sidx[r];
            float t0 = st[r * 3], t1 = st[r * 3 + 1], t2 = st[r * 3 + 2];
            float pr2 = fmaf(t0, w0c, fmaf(t1, w1c, fmaf(t2, w2c, bpc)));
            a = fmaf(g_xv[(size_t)j * 256 + c] + pr2, sh[pt * 528 + ns * 33 + jl], a);
        }
        out[(size_t)(n0 + pt) * 256 + c] = a;
    }
}

// ---------------- launch ----------------
extern "C" void kernel_launch(void* const* d_in, const int* in_sizes, int n_in,
                              void* d_out, int out_size)
{
    (void)in_sizes; (void)n_in; (void)out_size;
    const float* p   = (const float*)d_in[0];
    const float* x   = (const float*)d_in[1];
    const int*   idx = (const int*)  d_in[2];
    const float* wq  = (const float*)d_in[3];
    const float* bq  = (const float*)d_in[4];
    const float* wk  = (const float*)d_in[5];
    const float* bk  = (const float*)d_in[6];
    const float* wv  = (const float*)d_in[7];
    const float* bv  = (const float*)d_in[8];
    const float* wp1 = (const float*)d_in[9];
    const float* bp1 = (const float*)d_in[10];
    const float* gp  = (const float*)d_in[11];
    const float* btp = (const float*)d_in[12];
    const float* wp2 = (const float*)d_in[13];
    const float* bp2 = (const float*)d_in[14];
    const float* g1  = (const float*)d_in[15];
    const float* b1  = (const float*)d_in[16];
    const float* ww1 = (const float*)d_in[17];
    const float* bw1 = (const float*)d_in[18];
    const float* g2  = (const float*)d_in[19];
    const float* b2  = (const float*)d_in[20];
    const float* ww2 = (const float*)d_in[21];
    const float* bw2 = (const float*)d_in[22];
    float* out = (float*)d_out;

    cudaFuncSetAttribute(k_qkv_mma, cudaFuncAttributeMaxDynamicSharedMemorySize, QKV_SMEM);
    cudaFuncSetAttribute(k_h1, cudaFuncAttributeMaxDynamicSharedMemorySize, H1_SMEM);

    k_zero<<<1, 256>>>();
    k_cvt<<<4146, 256>>>(x, wq, wk, wv, ww1);
    k_qkv_mma<<<dim3(6, 512), 256, QKV_SMEM>>>(bq, bk, bv);
    k_pr1<<<1024, 256>>>(p, idx, wp1, bp1);
    k_bn1<<<2048, 256>>>(idx, wp2, bp2, gp, btp);
    k_h1<<<16384, 256, H1_SMEM>>>(idx, wp2, bp2, bw1, gp, btp, g1, b1);
    k_out<<<16384, 256>>>(idx, wp2, bp2, ww2, bw2, gp, btp, g2, b2, out);
}

// round 11
// speedup vs baseline: 1.9550x; 1.0162x over previous
#include <cuda_runtime.h>
#include <cuda_bf16.h>
#include <stdint.h>
#include <math.h>

#define NPTS   65536
#define NSAMP  16
#define CDIM   256
#define CH2    32
#define NROWS  (NPTS*NSAMP)   // 1048576
#define INVN   (1.0/(double)NROWS)

// ---------------- device scratch (static; no allocation allowed) ----------------
__device__ float g_xq[NPTS*CDIM];              // 64 MB
__device__ float g_xk[NPTS*CDIM];              // 64 MB
__device__ float g_xv[NPTS*CDIM];              // 64 MB
__device__ __nv_bfloat16 g_xh[NPTS*CDIM];      // 32 MB split-bf16 of x
__device__ __nv_bfloat16 g_xl[NPTS*CDIM];      // 32 MB
__device__ __nv_bfloat16 g_wh[768*CDIM];       // stacked [wq;wk;wv] hi
__device__ __nv_bfloat16 g_wl[768*CDIM];       // lo
__device__ __nv_bfloat16 g_w1h[CH2*CDIM];      // ww1 hi
__device__ __nv_bfloat16 g_w1l[CH2*CDIM];      // ww1 lo
__device__ float g_pr1[NROWS*3];               // 12 MB
__device__ float g_h1[NROWS*CH2];              // 128 MB
__device__ double g_sp[6];
__device__ double g_s1[512];
__device__ double g_s2[64];

// ---------------- mma / async helpers ----------------
__device__ __forceinline__ uint32_t smaddr(const void* p) {
    return (uint32_t)__cvta_generic_to_shared(p);
}
__device__ __forceinline__ void ldsm4(uint32_t a, uint32_t& r0, uint32_t& r1, uint32_t& r2, uint32_t& r3) {
    asm volatile("ldmatrix.sync.aligned.m8n8.x4.shared.b16 {%0,%1,%2,%3}, [%4];"
                 : "=r"(r0), "=r"(r1), "=r"(r2), "=r"(r3) : "r"(a));
}
__device__ __forceinline__ void ldsm2(uint32_t a, uint32_t& r0, uint32_t& r1) {
    asm volatile("ldmatrix.sync.aligned.m8n8.x2.shared.b16 {%0,%1}, [%2];"
                 : "=r"(r0), "=r"(r1) : "r"(a));
}
__device__ __forceinline__ void mma16816(float* c, const uint32_t* a, const uint32_t* b) {
    asm volatile("mma.sync.aligned.m16n8k16.row.col.f32.bf16.bf16.f32 "
                 "{%0,%1,%2,%3},{%4,%5,%6,%7},{%8,%9},{%0,%1,%2,%3};"
                 : "+f"(c[0]), "+f"(c[1]), "+f"(c[2]), "+f"(c[3])
                 : "r"(a[0]), "r"(a[1]), "r"(a[2]), "r"(a[3]), "r"(b[0]), "r"(b[1]));
}
__device__ __forceinline__ void cpasync16(uint32_t dst, const void* src) {
    asm volatile("cp.async.cg.shared.global [%0], [%1], 16;" :: "r"(dst), "l"(src));
}
__device__ __forceinline__ void cp_commit() {
    asm volatile("cp.async.commit_group;");
}
template<int N>
__device__ __forceinline__ void cp_wait() {
    asm volatile("cp.async.wait_group %0;" :: "n"(N));
}

// ---------------- K0: zero stat accumulators ----------------
__global__ void k_zero() {
    int t = threadIdx.x;
    if (t < 6) g_sp[t] = 0.0;
    for (int i = t; i < 512; i += 256) g_s1[i] = 0.0;
    if (t < 64) g_s2[t] = 0.0;
}

// ---------------- K_cvt: split-bf16 conversion of x, [wq;wk;wv], ww1 ----------
__global__ __launch_bounds__(256) void k_cvt(
    const float* __restrict__ x,
    const float* __restrict__ wq, const float* __restrict__ wk, const float* __restrict__ wv,
    const float* __restrict__ ww1)
{
    const int b = blockIdx.x, tid = threadIdx.x;
    const float* src;
    __nv_bfloat16 *dh, *dl;
    size_t off;
    if (b < 4096) {
        off = (size_t)b * 4096 + (size_t)tid * 16;
        src = x + off; dh = g_xh; dl = g_xl;
    } else if (b < 4144) {
        size_t i = (size_t)(b - 4096) * 4096 + (size_t)tid * 16;  // 0..196607
        off = i;
        int row = (int)(i >> 8);
        const float* w = (row < 256) ? wq : (row < 512) ? wk : wv;
        src = w + (size_t)(row & 255) * 256 + (i & 255);
        dh = g_wh; dl = g_wl;
    } else {
        size_t i = (size_t)(b - 4144) * 4096 + (size_t)tid * 16;  // 0..8191
        off = i; src = ww1 + i; dh = g_w1h; dl = g_w1l;
    }
#pragma unroll
    for (int j = 0; j < 4; j++) {
        float4 v = *(const float4*)(src + j * 4);
        __nv_bfloat16 h0 = __float2bfloat16(v.x);
        __nv_bfloat16 h1 = __float2bfloat16(v.y);
        __nv_bfloat16 h2 = __float2bfloat16(v.z);
        __nv_bfloat16 h3 = __float2bfloat16(v.w);
        __nv_bfloat16 l0 = __float2bfloat16(v.x - __bfloat162float(h0));
        __nv_bfloat16 l1 = __float2bfloat16(v.y - __bfloat162float(h1));
        __nv_bfloat16 l2 = __float2bfloat16(v.z - __bfloat162float(h2));
        __nv_bfloat16 l3 = __float2bfloat16(v.w - __bfloat162float(h3));
        *(__nv_bfloat162*)(dh + off + j * 4)     = __nv_bfloat162(h0, h1);
        *(__nv_bfloat162*)(dh + off + j * 4 + 2) = __nv_bfloat162(h2, h3);
        *(__nv_bfloat162*)(dl + off + j * 4)     = __nv_bfloat162(l0, l1);
        *(__nv_bfloat162*)(dl + off + j * 4 + 2) = __nv_bfloat162(l2, l3);
    }
}

// ---------------- K1: QKV via split-bf16 tensor-core GEMM, cp.async 2-stage ----
// C[65536,768] = x @ W^T + b.  Block tile 128x128, 8 warps (2x4), warp tile 64x32.
// K chunk 32, 2 smem stages.
#define QS2 40
#define STAGE_ELEMS (4*128*QS2)
#define QKV_SMEM (2*STAGE_ELEMS*2)   // 81920 B
__global__ __launch_bounds__(256, 2) void k_qkv_mma(
    const float* __restrict__ bq, const float* __restrict__ bk, const float* __restrict__ bv)
{
    extern __shared__ __nv_bfloat16 qs[];

    const int tid = threadIdx.x, wid = tid >> 5, lane = tid & 31;
    const int bx = blockIdx.x;
    const int m0 = blockIdx.y * 128;
    const int n0 = bx * 128;
    const int mw = wid & 1, nw = wid >> 1;

    float c[4][4][4];
#pragma unroll
    for (int i = 0; i < 4; i++)
#pragma unroll
        for (int j = 0; j < 4; j++)
#pragma unroll
            for (int r = 0; r < 4; r++) c[i][j][r] = 0.f;

    const int agrp = lane >> 3, ar = lane & 7;
    const int aRowOff = (agrp & 1) * 8 + ar;
    const int aColOff = (agrp >> 1) * 8;
    const int br = lane & 7, bg = (lane >> 3) & 1;

    // prefetch lambda-ish macro: load chunk kc into stage s
    // per thread: 2 chunks per array (id = tid, tid+256); row=id>>2, col=(id&3)*8
#define QKV_PREFETCH(s, kc) do {                                              \
        __nv_bfloat16* Ah_ = qs + (s) * STAGE_ELEMS;                          \
        __nv_bfloat16* Al_ = Ah_ + 128 * QS2;                                 \
        __nv_bfloat16* Bh_ = Al_ + 128 * QS2;                                 \
        __nv_bfloat16* Bl_ = Bh_ + 128 * QS2;                                 \
        const int kbase_ = (kc) * 32;                                         \
        _Pragma("unroll")                                                     \
        for (int i_ = 0; i_ < 2; i_++) {                                      \
            int id_ = tid + i_ * 256;                                         \
            int row_ = id_ >> 2, col_ = (id_ & 3) * 8;                        \
            size_t gA_ = (size_t)(m0 + row_) * 256 + kbase_ + col_;           \
            size_t gB_ = (size_t)(n0 + row_) * 256 + kbase_ + col_;           \
            cpasync16(smaddr(Ah_ + row_ * QS2 + col_), &g_xh[gA_]);           \
            cpasync16(smaddr(Al_ + row_ * QS2 + col_), &g_xl[gA_]);           \
            cpasync16(smaddr(Bh_ + row_ * QS2 + col_), &g_wh[gB_]);           \
            cpasync16(smaddr(Bl_ + row_ * QS2 + col_), &g_wl[gB_]);           \
        }                                                                     \
    } while (0)

    QKV_PREFETCH(0, 0);
    cp_commit();

    for (int kc = 0; kc < 8; kc++) {
        if (kc < 7) {
            QKV_PREFETCH((kc + 1) & 1, kc + 1);
            cp_commit();
            cp_wait<1>();
        } else {
            cp_wait<0>();
        }
        __syncthreads();

        const __nv_bfloat16* Ah = qs + (kc & 1) * STAGE_ELEMS;
        const __nv_bfloat16* Al = Ah + 128 * QS2;
        const __nv_bfloat16* Bh = Al + 128 * QS2;
        const __nv_bfloat16* Bl = Bh + 128 * QS2;
        const uint32_t aBaseH = smaddr(Ah), aBaseL = smaddr(Al);
        const uint32_t bBaseH = smaddr(Bh), bBaseL = smaddr(Bl);

#pragma unroll
        for (int ks = 0; ks < 2; ks++) {
            const int k0 = ks * 16;
            uint32_t bh[4][2], bl[4][2];
#pragma unroll
            for (int nt = 0; nt < 4; nt++) {
                int rowB = nw * 32 + nt * 8 + br;
                uint32_t off = (uint32_t)((rowB * QS2 + k0 + bg * 8) * 2);
                ldsm2(bBaseH + off, bh[nt][0], bh[nt][1]);
                ldsm2(bBaseL + off, bl[nt][0], bl[nt][1]);
            }
#pragma unroll
            for (int mt = 0; mt < 4; mt++) {
                int rowA = mw * 64 + mt * 16 + aRowOff;
                uint32_t off = (uint32_t)((rowA * QS2 + k0 + aColOff) * 2);
                uint32_t ah[4], al[4];
                ldsm4(aBaseH + off, ah[0], ah[1], ah[2], ah[3]);
                ldsm4(aBaseL + off, al[0], al[1], al[2], al[3]);
#pragma unroll
                for (int nt = 0; nt < 4; nt++) {
                    mma16816(c[mt][nt], ah, bh[nt]);
                    mma16816(c[mt][nt], ah, bl[nt]);
                    mma16816(c[mt][nt], al, bh[nt]);
                }
            }
        }
        __syncthreads();
    }

    const int buf = bx >> 1;
    float* Cout = (buf == 0) ? g_xq : (buf == 1) ? g_xk : g_xv;
    const float* Bias = (buf == 0) ? bq : (buf == 1) ? bk : bv;
    const int gr = lane >> 2, gc = lane & 3;
#pragma unroll
    for (int mt = 0; mt < 4; mt++) {
        int row = m0 + mw * 64 + mt * 16 + gr;
#pragma unroll
        for (int nt = 0; nt < 4; nt++) {
            int colg = (bx & 1) * 128 + nw * 32 + nt * 8 + gc * 2;
            float b0 = Bias[colg], b1 = Bias[colg + 1];
            *(float2*)&Cout[(size_t)row * 256 + colg] =
                make_float2(c[mt][nt][0] + b0, c[mt][nt][1] + b1);
            *(float2*)&Cout[(size_t)(row + 8) * 256 + colg] =
                make_float2(c[mt][nt][2] + b0, c[mt][nt][3] + b1);
        }
    }
}

// ---------------- K2: p_r1 + BN_p stats ----------------
__global__ __launch_bounds__(256) void k_pr1(
    const float* __restrict__ p, const int* __restrict__ idx,
    const float* __restrict__ wp1, const float* __restrict__ bp1)
{
    const int tid = threadIdx.x;
    const int base = blockIdx.x * 1024 + tid;
    float W[9], B[3];
#pragma unroll
    for (int i = 0; i < 9; i++) W[i] = wp1[i];
#pragma unroll
    for (int i = 0; i < 3; i++) B[i] = bp1[i];

    float v6[6] = {0, 0, 0, 0, 0, 0};
#pragma unroll
    for (int it = 0; it < 4; it++) {
        int i = base + it * 256;
        int n = i >> 4;
        int j = idx[i];
        float dx = p[j * 3 + 0] - p[n * 3 + 0];
        float dy = p[j * 3 + 1] - p[n * 3 + 1];
        float dz = p[j * 3 + 2] - p[n * 3 + 2];
        float r0 = fmaf(W[0], dx, fmaf(W[1], dy, fmaf(W[2], dz, B[0])));
        float r1 = fmaf(W[3], dx, fmaf(W[4], dy, fmaf(W[5], dz, B[1])));
        float r2 = fmaf(W[6], dx, fmaf(W[7], dy, fmaf(W[8], dz, B[2])));
        g_pr1[(size_t)i * 3 + 0] = r0;
        g_pr1[(size_t)i * 3 + 1] = r1;
        g_pr1[(size_t)i * 3 + 2] = r2;
        v6[0] += r0; v6[1] += r1; v6[2] += r2;
        v6[3] = fmaf(r0, r0, v6[3]);
        v6[4] = fmaf(r1, r1, v6[4]);
        v6[5] = fmaf(r2, r2, v6[5]);
    }
#pragma unroll
    for (int i = 0; i < 6; i++)
        for (int off = 16; off; off >>= 1)
            v6[i] += __shfl_down_sync(0xffffffffu, v6[i], off);

    __shared__ float wsum[8][6];
    int warp = tid >> 5, lane = tid & 31;
    if (lane == 0)
#pragma unroll
        for (int i = 0; i < 6; i++) wsum[warp][i] = v6[i];
    __syncthreads();
    if (tid < 6) {
        float tot = 0;
#pragma unroll
        for (int w = 0; w < 8; w++) tot += wsum[w][tid];
        atomicAdd(&g_sp[tid], (double)tot);
    }
}

// ---------------- K3: BN_1 stats ----------------
__global__ __launch_bounds__(256) void k_bn1(
    const int* __restrict__ idx,
    const float* __restrict__ wp2, const float* __restrict__ bp2,
    const float* __restrict__ gp, const float* __restrict__ btp)
{
    __shared__ int sidx[512];
    __shared__ float st[1536];
    __shared__ float sap[3], sdp[3];
    const int tid = threadIdx.x;
    const int n0 = blockIdx.x * 32;

    if (tid < 3) {
        double m = g_sp[tid] * INVN;
        double v = g_sp[3 + tid] * INVN - m * m;
        float a = (float)((double)gp[tid] / sqrt(v + 1e-5));
        sap[tid] = a; sdp[tid] = btp[tid] - (float)m * a;
    }
    for (int i = tid; i < 512; i += 256) sidx[i] = idx[n0 * 16 + i];
    for (int i = tid; i < 1536; i += 256) st[i] = g_pr1[(size_t)n0 * 48 + i];
    __syncthreads();
    for (int i = tid; i < 1536; i += 256) {
        int k = i % 3;
        st[i] = fmaxf(fmaf(sap[k], st[i], sdp[k]), 0.f);
    }
    const int c = tid;
    const float w0c = wp2[c * 3], w1c = wp2[c * 3 + 1], w2c = wp2[c * 3 + 2];
    const float bpc = bp2[c];
    float s = 0.f, q = 0.f;
    __syncthreads();

    for (int pt = 0; pt < 32; pt++) {
        float xqc = g_xq[(size_t)(n0 + pt) * 256 + c];
        int b16 = pt * 16;
#pragma unroll 4
        for (int ns = 0; ns < 16; ns++) {
            int j = sidx[b16 + ns];
            float t0 = st[(b16 + ns) * 3], t1 = st[(b16 + ns) * 3 + 1], t2 = st[(b16 + ns) * 3 + 2];
            float pr2 = fmaf(t0, w0c, fmaf(t1, w1c, fmaf(t2, w2c, bpc)));
            float w = g_xk[(size_t)j * 256 + c] - xqc + pr2;
            s += w;
            q = fmaf(w, w, q);
        }
    }
    atomicAdd(&g_s1[c], (double)s);
    atomicAdd(&g_s1[256 + c], (double)q);
}

// ---------------- K4: h1 via gather + split-bf16 tensor-core GEMM ---------------
#define HS 264
#define H1_SMEM ((192*HS)*2 + 64*36*4)   // 101376 + 9216 = 110592 B
__global__ __launch_bounds__(256, 2) void k_h1(
    const int* __restrict__ idx,
    const float* __restrict__ wp2, const float* __restrict__ bp2,
    const float* __restrict__ bw1,
    const float* __restrict__ gp, const float* __restrict__ btp,
    const float* __restrict__ g1, const float* __restrict__ b1)
{
    extern __shared__ __nv_bfloat16 hsm[];
    __nv_bfloat16* uh = hsm;                  // [64][HS]
    __nv_bfloat16* ul = uh + 64 * HS;
    __nv_bfloat16* wh = ul + 64 * HS;         // [32][HS]
    __nv_bfloat16* wl = wh + 32 * HS;
    float* Ctmp = (float*)(wl + 32 * HS);     // [64][36]
    __shared__ int sidx[64];
    __shared__ float st[192];
    __shared__ float ssum[32], ssq[32];
    __shared__ float sap[3], sdp[3];

    const int tid = threadIdx.x, wid = tid >> 5, lane = tid & 31;
    const int n0 = blockIdx.x * 4;
    const int r0g = blockIdx.x * 64;

    if (tid < 3) {
        double m = g_sp[tid] * INVN;
        double v = g_sp[3 + tid] * INVN - m * m;
        float a = (float)((double)gp[tid] / sqrt(v + 1e-5));
        sap[tid] = a; sdp[tid] = btp[tid] - (float)m * a;
    }
    if (tid < 64) sidx[tid] = idx[r0g + tid];
    if (tid < 32) { ssum[tid] = 0.f; ssq[tid] = 0.f; }
    if (tid < 192) st[tid] = g_pr1[(size_t)n0 * 48 + tid];
#pragma unroll
    for (int i = 0; i < 4; i++) {
        int id = tid + i * 256;
        int row = id >> 5, col8 = id & 31;
        *(uint4*)&wh[row * HS + col8 * 8] = *(const uint4*)&g_w1h[row * 256 + col8 * 8];
        *(uint4*)&wl[row * HS + col8 * 8] = *(const uint4*)&g_w1l[row * 256 + col8 * 8];
    }

    const int c = tid;
    float a1c, d1c;
    {
        double m = g_s1[c] * INVN;
        double v = g_s1[256 + c] * INVN - m * m;
        a1c = (float)((double)g1[c] / sqrt(v + 1e-5));
        d1c = b1[c] - (float)m * a1c;
    }
    float xqr[4];
#pragma unroll
    for (int pt = 0; pt < 4; pt++) xqr[pt] = g_xq[(size_t)(n0 + pt) * 256 + c];
    const float w0c = wp2[c * 3], w1c = wp2[c * 3 + 1], w2c = wp2[c * 3 + 2];
    const float bpc = bp2[c];
    __syncthreads();

    if (tid < 192) {
        int k = tid % 3;
        st[tid] = fmaxf(fmaf(sap[k], st[tid], sdp[k]), 0.f);
    }
    __syncthreads();

    // phase 1: gather + bn1 + relu -> split bf16 into smem
#pragma unroll 4
    for (int r = 0; r < 64; r++) {
        int j = sidx[r];
        float t0 = st[r * 3], t1 = st[r * 3 + 1], t2 = st[r * 3 + 2];
        float pr2 = fmaf(t0, w0c, fmaf(t1, w1c, fmaf(t2, w2c, bpc)));
        float w = g_xk[(size_t)j * 256 + c] - xqr[r >> 4] + pr2;
        float u = fmaxf(fmaf(a1c, w, d1c), 0.f);
        __nv_bfloat16 h = __float2bfloat16(u);
        uh[r * HS + c] = h;
        ul[r * HS + c] = __float2bfloat16(u - __bfloat162float(h));
    }
    __syncthreads();

    // phase 2: C[64][32] = u @ ww1^T via mma
    const int mt = wid & 3, kh = wid >> 2;
    float c4[4][4];
#pragma unroll
    for (int nt = 0; nt < 4; nt++)
#pragma unroll
        for (int r = 0; r < 4; r++) c4[nt][r] = 0.f;

    const uint32_t uBaseH = smaddr(uh), uBaseL = smaddr(ul);
    const uint32_t wBaseH = smaddr(wh), wBaseL = smaddr(wl);
    const int agrp = lane >> 3, ar = lane & 7;
    const int aRowOff = (agrp & 1) * 8 + ar;
    const int aColOff = (agrp >> 1) * 8;
    const int br = lane & 7, bg = (lane >> 3) & 1;

#pragma unroll
    for (int ks = 0; ks < 8; ks++) {
        const int k0 = kh * 128 + ks * 16;
        uint32_t bh[4][2], bl[4][2];
#pragma unroll
        for (int nt = 0; nt < 4; nt++) {
            uint32_t off = (uint32_t)(((nt * 8 + br) * HS + k0 + bg * 8) * 2);
            ldsm2(wBaseH + off, bh[nt][0], bh[nt][1]);
            ldsm2(wBaseL + off, bl[nt][0], bl[nt][1]);
        }
        uint32_t ah[4], al[4];
        uint32_t offA = (uint32_t)(((mt * 16 + aRowOff) * HS + k0 + aColOff) * 2);
        ldsm4(uBaseH + offA, ah[0], ah[1], ah[2], ah[3]);
        ldsm4(uBaseL + offA, al[0], al[1], al[2], al[3]);
#pragma unroll
        for (int nt = 0; nt < 4; nt++) {
            mma16816(c4[nt], ah, bh[nt]);
            mma16816(c4[nt], ah, bl[nt]);
            mma16816(c4[nt], al, bh[nt]);
        }
    }

    const int gr = lane >> 2, gc = lane & 3;
    if (wid < 4) {
#pragma unroll
        for (int nt = 0; nt < 4; nt++) {
            Ctmp[(mt * 16 + gr) * 36 + nt * 8 + gc * 2]         = c4[nt][0];
            Ctmp[(mt * 16 + gr) * 36 + nt * 8 + gc * 2 + 1]     = c4[nt][1];
            Ctmp[(mt * 16 + gr + 8) * 36 + nt * 8 + gc * 2]     = c4[nt][2];
            Ctmp[(mt * 16 + gr + 8) * 36 + nt * 8 + gc * 2 + 1] = c4[nt][3];
        }
    }
    __syncthreads();
    if (wid >= 4) {
#pragma unroll
        for (int nt = 0; nt < 4; nt++) {
            Ctmp[(mt * 16 + gr) * 36 + nt * 8 + gc * 2]         += c4[nt][0];
            Ctmp[(mt * 16 + gr) * 36 + nt * 8 + gc * 2 + 1]     += c4[nt][1];
            Ctmp[(mt * 16 + gr + 8) * 36 + nt * 8 + gc * 2]     += c4[nt][2];
            Ctmp[(mt * 16 + gr + 8) * 36 + nt * 8 + gc * 2 + 1] += c4[nt][3];
        }
    }
    __syncthreads();

    // epilogue: bias, store h1 (coalesced), BN2 stats
    {
        const int col = tid & 31;
        const int rg = tid >> 5;
        const float bw = bw1[col];
        float s = 0.f, q = 0.f;
#pragma unroll
        for (int i = 0; i < 8; i++) {
            int r = rg * 8 + i;
            float v = Ctmp[r * 36 + col] + bw;
            g_h1[(size_t)(r0g + r) * 32 + col] = v;
            s += v;
            q = fmaf(v, v, q);
        }
        atomicAdd(&ssum[col], s);
        atomicAdd(&ssq[col], q);
    }
    __syncthreads();
    if (tid < 32) {
        atomicAdd(&g_s2[tid], (double)ssum[tid]);
        atomicAdd(&g_s2[32 + tid], (double)ssq[tid]);
    }
}

// ---------------- K5: bn2+relu -> @ww2 -> softmax(ns) -> weighted gather-sum ----
// 8 points per block.
__global__ __launch_bounds__(256) void k_out(
    const int* __restrict__ idx,
    const float* __restrict__ wp2, const float* __restrict__ bp2,
    const float* __restrict__ ww2, const float* __restrict__ bw2,
    const float* __restrict__ gp, const float* __restrict__ btp,
    const float* __restrict__ g2, const float* __restrict__ b2,
    float* __restrict__ out)
{
    __shared__ int sidx[128];
    __shared__ float st[384];
    __shared__ float sv[4096];          // [pt][ns][k] bn2-relu'd h1
    __shared__ float sw2t[32 * 36];     // [j][k] transposed ww2
    __shared__ float sh[8 * 528];       // [pt][ns*33 + k] logits/softmax
    __shared__ float sbw[32];
    __shared__ float sa2[32], sd2[32];
    __shared__ float sap[3], sdp[3];

    const int tid = threadIdx.x;
    const int n0 = blockIdx.x * 8;

    if (tid < 3) {
        double m = g_sp[tid] * INVN;
        double v = g_sp[3 + tid] * INVN - m * m;
        float a = (float)((double)gp[tid] / sqrt(v + 1e-5));
        sap[tid] = a; sdp[tid] = btp[tid] - (float)m * a;
    }
    if (tid >= 32 && tid < 64) {
        int k = tid - 32;
        double m = g_s2[k] * INVN;
        double v = g_s2[32 + k] * INVN - m * m;
        float a = (float)((double)g2[k] / sqrt(v + 1e-5));
        sa2[k] = a; sd2[k] = b2[k] - (float)m * a;
    }
    if (tid < 128) sidx[tid] = idx[n0 * 16 + tid];
    if (tid >= 128 && tid < 160) sbw[tid - 128] = bw2[tid - 128];
    for (int f = tid; f < 1024; f += 256) sw2t[(f & 31) * 36 + (f >> 5)] = ww2[f];
    __syncthreads();

    // st: bn_p + relu on p_r1 for 8 pts (384 values)
    if (tid < 128) {
#pragma unroll
        for (int rep = 0; rep < 3; rep++) {
            int i = tid + rep * 128;
            int k = i % 3;
            float v = g_pr1[(size_t)n0 * 48 + i];
            st[i] = fmaxf(fmaf(sap[k], v, sdp[k]), 0.f);
        }
    }
#pragma unroll
    for (int rep = 0; rep < 16; rep++) {
        int i = tid + rep * 256;
        int k = i & 31;
        float hv = g_h1[(size_t)n0 * 512 + i];
        sv[i] = fmaxf(fmaf(sa2[k], hv, sd2[k]), 0.f);
    }
    __syncthreads();

    // logits: thread -> (pt,ns) pair (tid>>1) + 16 output channels ((tid&1)*16)
    {
        const int pair = tid >> 1;                 // 0..127 = pt*16+ns
        const int kq = (tid & 1) * 16;
        float a[16];
#pragma unroll
        for (int r = 0; r < 16; r += 4) {
            float4 bwv = *(float4*)&sbw[kq + r];
            a[r] = bwv.x; a[r + 1] = bwv.y; a[r + 2] = bwv.z; a[r + 3] = bwv.w;
        }
#pragma unroll 4
        for (int j = 0; j < 32; j++) {
            float s = sv[pair * 32 + j];
#pragma unroll
            for (int r = 0; r < 16; r += 4) {
                float4 w = *(float4*)&sw2t[j * 36 + kq + r];
                a[r]     = fmaf(s, w.x, a[r]);
                a[r + 1] = fmaf(s, w.y, a[r + 1]);
                a[r + 2] = fmaf(s, w.z, a[r + 2]);
                a[r + 3] = fmaf(s, w.w, a[r + 3]);
            }
        }
        int pt = pair >> 4, ns = pair & 15;
#pragma unroll
        for (int r = 0; r < 16; r++) sh[pt * 528 + ns * 33 + kq + r] = a[r];
    }
    __syncthreads();

    // softmax over ns (16) for each (pt, k): 256 threads = 8 pts x 32 ch
    {
        int pt = tid >> 5, k = tid & 31;
        float* row = &sh[pt * 528 + k];
        float m = -1e30f;
#pragma unroll
        for (int ns = 0; ns < 16; ns++) m = fmaxf(m, row[ns * 33]);
        float s = 0.f;
#pragma unroll
        for (int ns = 0; ns < 16; ns++) {
            float e = expf(row[ns * 33] - m);
            row[ns * 33] = e;
            s += e;
        }
        float inv = 1.f / s;
#pragma unroll
        for (int ns = 0; ns < 16; ns++) row[ns * 33] *= inv;
    }
    __syncthreads();

    // weighted gather-sum
    const int c = tid;
    const float w0c = wp2[c * 3], w1c = wp2[c * 3 + 1], w2c = wp2[c * 3 + 2];
    const float bpc = bp2[c];
    const int jl = c & 31;
#pragma unroll
    for (int pt = 0; pt < 8; pt++) {
        float a = 0.f;
#pragma unroll 4
        for (int ns = 0; ns < 16; ns++) {
            int r = pt * 16 + ns;
            int j = sidx[r];
            float t0 = st[r * 3], t1 = st[r * 3 + 1], t2 = st[r * 3 + 2];
            float pr2 = fmaf(t0, w0c, fmaf(t1, w1c, fmaf(t2, w2c, bpc)));
            a = fmaf(g_xv[(size_t)j * 256 + c] + pr2, sh[pt * 528 + ns * 33 + jl], a);
        }
        out[(size_t)(n0 + pt) * 256 + c] = a;
    }
}

// ---------------- launch ----------------
extern "C" void kernel_launch(void* const* d_in, const int* in_sizes, int n_in,
                              void* d_out, int out_size)
{
    (void)in_sizes; (void)n_in; (void)out_size;
    const float* p   = (const float*)d_in[0];
    const float* x   = (const float*)d_in[1];
    const int*   idx = (const int*)  d_in[2];
    const float* wq  = (const float*)d_in[3];
    const float* bq  = (const float*)d_in[4];
    const float* wk  = (const float*)d_in[5];
    const float* bk  = (const float*)d_in[6];
    const float* wv  = (const float*)d_in[7];
    const float* bv  = (const float*)d_in[8];
    const float* wp1 = (const float*)d_in[9];
    const float* bp1 = (const float*)d_in[10];
    const float* gp  = (const float*)d_in[11];
    const float* btp = (const float*)d_in[12];
    const float* wp2 = (const float*)d_in[13];
    const float* bp2 = (const float*)d_in[14];
    const float* g1  = (const float*)d_in[15];
    const float* b1  = (const float*)d_in[16];
    const float* ww1 = (const float*)d_in[17];
    const float* bw1 = (const float*)d_in[18];
    const float* g2  = (const float*)d_in[19];
    const float* b2  = (const float*)d_in[20];
    const float* ww2 = (const float*)d_in[21];
    const float* bw2 = (const float*)d_in[22];
    float* out = (float*)d_out;

    cudaFuncSetAttribute(k_qkv_mma, cudaFuncAttributeMaxDynamicSharedMemorySize, QKV_SMEM);
    cudaFuncSetAttribute(k_h1, cudaFuncAttributeMaxDynamicSharedMemorySize, H1_SMEM);

    k_zero<<<1, 256>>>();
    k_cvt<<<4146, 256>>>(x, wq, wk, wv, ww1);
    k_pr1<<<1024, 256>>>(p, idx, wp1, bp1);
    k_qkv_mma<<<dim3(6, 512), 256, QKV_SMEM>>>(bq, bk, bv);
    k_bn1<<<2048, 256>>>(idx, wp2, bp2, gp, btp);
    k_h1<<<16384, 256, H1_SMEM>>>(idx, wp2, bp2, bw1, gp, btp, g1, b1);
    k_out<<<8192, 256>>>(idx, wp2, bp2, ww2, bw2, gp, btp, g2, b2, out);
}